// round 1
// baseline (speedup 1.0000x reference)
#include <cuda_runtime.h>

// Problem constants
#define Dn 24
#define Cn 16
#define Hn 96
#define Wn 192
#define HWn (Hn * Wn)          // 18432
#define Pn (Dn * HWn)          // 442368 pixels
// x layout: x[c*Pn + p], p = d*HWn + h*Wn + w  (matches cost_volume memory order)

// Scratch (device globals — no allocation allowed)
__device__ float g_q[Pn * 2];
__device__ float g_k[Pn * 2];
__device__ float g_v[Pn * 16];     // channels-last per pixel
__device__ float g_y[Pn * 16];     // intermediate image (x layout: [c][p])
__device__ float g_mH[Pn];
__device__ float g_sH[Pn];
__device__ float g_oH[Pn * 16];    // unnormalized out_H, channels-last

// ---------------------------------------------------------------------------
// Kernel 1: QKV projection. One thread per pixel.
// ---------------------------------------------------------------------------
__global__ void qkv_kernel(const float* __restrict__ xin,
                           const float* __restrict__ qw, const float* __restrict__ qb,
                           const float* __restrict__ kw, const float* __restrict__ kb,
                           const float* __restrict__ vw, const float* __restrict__ vb)
{
    __shared__ float s_qw[32], s_kw[32], s_vw[256], s_qb[2], s_kb[2], s_vb[16];
    const float* x = xin ? xin : g_y;

    int t = threadIdx.x;
    for (int i = t; i < 256; i += blockDim.x) s_vw[i] = vw[i];
    if (t < 32)              s_qw[t]      = qw[t];
    else if (t < 64)         s_kw[t - 32] = kw[t - 32];
    else if (t < 66)         s_qb[t - 64] = qb[t - 64];
    else if (t < 68)         s_kb[t - 66] = kb[t - 66];
    else if (t < 84)         s_vb[t - 68] = vb[t - 68];
    __syncthreads();

    int p = blockIdx.x * blockDim.x + threadIdx.x;
    if (p >= Pn) return;

    float xv[16];
#pragma unroll
    for (int c = 0; c < 16; c++) xv[c] = x[c * Pn + p];

    float q0 = s_qb[0], q1 = s_qb[1], k0 = s_kb[0], k1 = s_kb[1];
#pragma unroll
    for (int c = 0; c < 16; c++) {
        q0 = fmaf(s_qw[c],      xv[c], q0);
        q1 = fmaf(s_qw[16 + c], xv[c], q1);
        k0 = fmaf(s_kw[c],      xv[c], k0);
        k1 = fmaf(s_kw[16 + c], xv[c], k1);
    }
    ((float2*)g_q)[p] = make_float2(q0, q1);
    ((float2*)g_k)[p] = make_float2(k0, k1);

    float vo[16];
#pragma unroll
    for (int o = 0; o < 16; o++) {
        float acc = s_vb[o];
#pragma unroll
        for (int c = 0; c < 16; c++) acc = fmaf(s_vw[o * 16 + c], xv[c], acc);
        vo[o] = acc;
    }
    float4* vp = (float4*)(g_v + p * 16);
#pragma unroll
    for (int i = 0; i < 4; i++)
        vp[i] = make_float4(vo[4 * i], vo[4 * i + 1], vo[4 * i + 2], vo[4 * i + 3]);
}

// ---------------------------------------------------------------------------
// Pass A: H-direction (column) partial softmax + aggregation.
// Block = one (d, w) column, thread = h.
// ---------------------------------------------------------------------------
__global__ __launch_bounds__(Hn) void passA_kernel()
{
    int w = blockIdx.x;
    int d = blockIdx.y;
    int h = threadIdx.x;

    __shared__ float2 s_k[Hn];
    __shared__ float4 s_v[Hn][4];

    int p = d * HWn + h * Wn + w;
    float2 q = ((const float2*)g_q)[p];
    s_k[h] = ((const float2*)g_k)[p];
    const float4* vp = (const float4*)(g_v + p * 16);
    s_v[h][0] = vp[0]; s_v[h][1] = vp[1]; s_v[h][2] = vp[2]; s_v[h][3] = vp[3];
    __syncthreads();

    // max (diag masked)
    float m = -1e30f;
#pragma unroll 8
    for (int j = 0; j < Hn; j++) {
        float e = fmaf(q.x, s_k[j].x, q.y * s_k[j].y);
        if (j == h) e = -1e9f;
        m = fmaxf(m, e);
    }

    float s = 0.f;
    float out[16];
#pragma unroll
    for (int c = 0; c < 16; c++) out[c] = 0.f;

#pragma unroll 4
    for (int j = 0; j < Hn; j++) {
        float e = fmaf(q.x, s_k[j].x, q.y * s_k[j].y);
        float pj = (j == h) ? 0.f : __expf(e - m);
        s += pj;
        float4 v0 = s_v[j][0], v1 = s_v[j][1], v2 = s_v[j][2], v3 = s_v[j][3];
        out[0]  = fmaf(pj, v0.x, out[0]);  out[1]  = fmaf(pj, v0.y, out[1]);
        out[2]  = fmaf(pj, v0.z, out[2]);  out[3]  = fmaf(pj, v0.w, out[3]);
        out[4]  = fmaf(pj, v1.x, out[4]);  out[5]  = fmaf(pj, v1.y, out[5]);
        out[6]  = fmaf(pj, v1.z, out[6]);  out[7]  = fmaf(pj, v1.w, out[7]);
        out[8]  = fmaf(pj, v2.x, out[8]);  out[9]  = fmaf(pj, v2.y, out[9]);
        out[10] = fmaf(pj, v2.z, out[10]); out[11] = fmaf(pj, v2.w, out[11]);
        out[12] = fmaf(pj, v3.x, out[12]); out[13] = fmaf(pj, v3.y, out[13]);
        out[14] = fmaf(pj, v3.z, out[14]); out[15] = fmaf(pj, v3.w, out[15]);
    }

    g_mH[p] = m;
    g_sH[p] = s;
    float4* op = (float4*)(g_oH + p * 16);
#pragma unroll
    for (int i = 0; i < 4; i++)
        op[i] = make_float4(out[4 * i], out[4 * i + 1], out[4 * i + 2], out[4 * i + 3]);
}

// ---------------------------------------------------------------------------
// Pass B: W-direction (row) partials + joint-softmax combine + residual.
// Block = one (d, h) row, thread = w.
// ---------------------------------------------------------------------------
__global__ __launch_bounds__(Wn) void passB_kernel(const float* __restrict__ xin,
                                                   float* __restrict__ dst,
                                                   const float* __restrict__ gammap)
{
    int h = blockIdx.x;
    int d = blockIdx.y;
    int w = threadIdx.x;

    __shared__ float2 s_k[Wn];
    __shared__ float4 s_v[Wn][4];

    const float* x = xin ? xin : g_y;
    float*       y = dst ? dst : g_y;

    int p = d * HWn + h * Wn + w;
    float2 q = ((const float2*)g_q)[p];
    s_k[w] = ((const float2*)g_k)[p];
    const float4* vp = (const float4*)(g_v + p * 16);
    s_v[w][0] = vp[0]; s_v[w][1] = vp[1]; s_v[w][2] = vp[2]; s_v[w][3] = vp[3];
    __syncthreads();

    float m = -1e30f;
#pragma unroll 8
    for (int j = 0; j < Wn; j++) {
        float e = fmaf(q.x, s_k[j].x, q.y * s_k[j].y);
        m = fmaxf(m, e);
    }

    float s = 0.f;
    float out[16];
#pragma unroll
    for (int c = 0; c < 16; c++) out[c] = 0.f;

#pragma unroll 4
    for (int j = 0; j < Wn; j++) {
        float e = fmaf(q.x, s_k[j].x, q.y * s_k[j].y);
        float pj = __expf(e - m);
        s += pj;
        float4 v0 = s_v[j][0], v1 = s_v[j][1], v2 = s_v[j][2], v3 = s_v[j][3];
        out[0]  = fmaf(pj, v0.x, out[0]);  out[1]  = fmaf(pj, v0.y, out[1]);
        out[2]  = fmaf(pj, v0.z, out[2]);  out[3]  = fmaf(pj, v0.w, out[3]);
        out[4]  = fmaf(pj, v1.x, out[4]);  out[5]  = fmaf(pj, v1.y, out[5]);
        out[6]  = fmaf(pj, v1.z, out[6]);  out[7]  = fmaf(pj, v1.w, out[7]);
        out[8]  = fmaf(pj, v2.x, out[8]);  out[9]  = fmaf(pj, v2.y, out[9]);
        out[10] = fmaf(pj, v2.z, out[10]); out[11] = fmaf(pj, v2.w, out[11]);
        out[12] = fmaf(pj, v3.x, out[12]); out[13] = fmaf(pj, v3.y, out[13]);
        out[14] = fmaf(pj, v3.z, out[14]); out[15] = fmaf(pj, v3.w, out[15]);
    }

    // combine with H-direction partials (joint softmax over H+W)
    float mH = g_mH[p];
    float sH = g_sH[p];
    float mm = fmaxf(m, mH);
    float aW = __expf(m - mm);
    float aH = __expf(mH - mm);
    float Z  = fmaf(s, aW, sH * aH);
    float inv = __fdividef(1.f, Z);
    float gamma = gammap[0];

    const float4* ohp = (const float4*)(g_oH + p * 16);
    float oh[16];
#pragma unroll
    for (int i = 0; i < 4; i++) {
        float4 t = ohp[i];
        oh[4 * i] = t.x; oh[4 * i + 1] = t.y; oh[4 * i + 2] = t.z; oh[4 * i + 3] = t.w;
    }

#pragma unroll
    for (int c = 0; c < 16; c++) {
        float o = (out[c] * aW + oh[c] * aH) * inv;
        y[c * Pn + p] = fmaf(gamma, o, x[c * Pn + p]);
    }
}

// ---------------------------------------------------------------------------
extern "C" void kernel_launch(void* const* d_in, const int* in_sizes, int n_in,
                              void* d_out, int out_size)
{
    const float* x     = (const float*)d_in[0];
    const float* qw    = (const float*)d_in[1];
    const float* qb    = (const float*)d_in[2];
    const float* kw    = (const float*)d_in[3];
    const float* kb    = (const float*)d_in[4];
    const float* vw    = (const float*)d_in[5];
    const float* vb    = (const float*)d_in[6];
    const float* gamma = (const float*)d_in[7];
    float* out = (float*)d_out;

    dim3 gA(Wn, Dn);   // 192 x 24 blocks, 96 threads
    dim3 gB(Hn, Dn);   // 96 x 24 blocks, 192 threads
    int qkvBlocks = Pn / 256;  // 1728 exact

    // ---- iteration 1: read x, write g_y ----
    qkv_kernel<<<qkvBlocks, 256>>>(x, qw, qb, kw, kb, vw, vb);
    passA_kernel<<<gA, Hn>>>();
    passB_kernel<<<gB, Wn>>>(x, nullptr, gamma);

    // ---- iteration 2: read g_y, write d_out ----
    qkv_kernel<<<qkvBlocks, 256>>>(nullptr, qw, qb, kw, kb, vw, vb);
    passA_kernel<<<gA, Hn>>>();
    passB_kernel<<<gB, Wn>>>(nullptr, out, gamma);
}

// round 2
// speedup vs baseline: 1.1553x; 1.1553x over previous
#include <cuda_runtime.h>

#define Dn 24
#define Hn 96
#define Wn 192
#define HWn (Hn * Wn)          // 18432
#define Pn (Dn * HWn)          // 442368

typedef unsigned long long ull;

// Scratch (device globals — allocation forbidden)
__device__ float g_q[Pn * 2];      // [p][2], q pre-scaled by log2(e)
__device__ float g_k[Pn * 2];      // [p][2]
__device__ ull   g_v[Pn * 8];      // [p][8] channel pairs packed as f32x2
__device__ float g_y[Pn * 16];     // intermediate image, [c][p]
__device__ float g_mH[Pn];
__device__ float g_sH[Pn];
__device__ ull   g_oH[Pn * 8];     // unnormalized out_H, channel pairs

// ---- f32x2 helpers -------------------------------------------------------
__device__ __forceinline__ void F2(ull& d, ull a, ull b, ull c) {
    asm("fma.rn.f32x2 %0,%1,%2,%3;" : "=l"(d) : "l"(a), "l"(b), "l"(c));
}
__device__ __forceinline__ void M2(ull& d, ull a, ull b) {
    asm("mul.rn.f32x2 %0,%1,%2;" : "=l"(d) : "l"(a), "l"(b));
}
__device__ __forceinline__ void A2(ull& d, ull a, ull b) {
    asm("add.rn.f32x2 %0,%1,%2;" : "=l"(d) : "l"(a), "l"(b));
}
__device__ __forceinline__ ull pack2(float lo, float hi) {
    ull r; asm("mov.b64 %0,{%1,%2};" : "=l"(r) : "f"(lo), "f"(hi)); return r;
}
__device__ __forceinline__ ull dup2(float v) { return pack2(v, v); }
__device__ __forceinline__ float2 unpack2(ull v) {
    float2 r; asm("mov.b64 {%0,%1},%2;" : "=f"(r.x), "=f"(r.y) : "l"(v)); return r;
}
__device__ __forceinline__ float ex2f(float x) {
    float r; asm("ex2.approx.ftz.f32 %0,%1;" : "=f"(r) : "f"(x)); return r;
}

#define L2E 1.44269504088896340736f

// ---------------------------------------------------------------------------
// QKV projection. One thread per pixel; v projection in channel-paired f32x2.
// ---------------------------------------------------------------------------
__global__ __launch_bounds__(256) void qkv_kernel(const float* __restrict__ xin,
                           const float* __restrict__ qw, const float* __restrict__ qb,
                           const float* __restrict__ kw, const float* __restrict__ kb,
                           const float* __restrict__ vw, const float* __restrict__ vb)
{
    __shared__ float s_qw[32], s_kw[32], s_qb[2], s_kb[2];
    __shared__ ull s_vw[16][8];   // [c][opair] = {vw[2o][c], vw[2o+1][c]}
    __shared__ ull s_vb[8];
    const float* x = xin ? xin : g_y;

    int t = threadIdx.x;
    if (t < 128) {
        int c = t & 15, j = t >> 4;
        s_vw[c][j] = pack2(vw[(2 * j) * 16 + c], vw[(2 * j + 1) * 16 + c]);
    } else if (t < 160)  s_qw[t - 128] = qw[t - 128];
    else if (t < 192)    s_kw[t - 160] = kw[t - 160];
    else if (t < 194)    s_qb[t - 192] = qb[t - 192];
    else if (t < 196)    s_kb[t - 194] = kb[t - 194];
    else if (t < 204)    s_vb[t - 196] = pack2(vb[2 * (t - 196)], vb[2 * (t - 196) + 1]);
    __syncthreads();

    int p = blockIdx.x * 256 + t;

    float xv[16];
#pragma unroll
    for (int c = 0; c < 16; c++) xv[c] = x[c * Pn + p];

    float q0 = s_qb[0], q1 = s_qb[1], k0 = s_kb[0], k1 = s_kb[1];
#pragma unroll
    for (int c = 0; c < 16; c++) {
        q0 = fmaf(s_qw[c],      xv[c], q0);
        q1 = fmaf(s_qw[16 + c], xv[c], q1);
        k0 = fmaf(s_kw[c],      xv[c], k0);
        k1 = fmaf(s_kw[16 + c], xv[c], k1);
    }
    ((float2*)g_q)[p] = make_float2(q0 * L2E, q1 * L2E);   // fold log2(e) into q
    ((float2*)g_k)[p] = make_float2(k0, k1);

    ull av[8];
#pragma unroll
    for (int j = 0; j < 8; j++) av[j] = s_vb[j];
#pragma unroll
    for (int c = 0; c < 16; c++) {
        ull xc2 = dup2(xv[c]);
#pragma unroll
        for (int j = 0; j < 8; j++) F2(av[j], s_vw[c][j], xc2, av[j]);
    }
    ulonglong2* vp = (ulonglong2*)&g_v[p * 8];
    vp[0] = make_ulonglong2(av[0], av[1]);
    vp[1] = make_ulonglong2(av[2], av[3]);
    vp[2] = make_ulonglong2(av[4], av[5]);
    vp[3] = make_ulonglong2(av[6], av[7]);
}

// ---------------------------------------------------------------------------
// Pass A: H-direction partial softmax + aggregation. Block = (d, w) column.
// ---------------------------------------------------------------------------
__global__ __launch_bounds__(Hn) void passA_kernel()
{
    __shared__ __align__(8) float s_kx[Hn], s_ky[Hn];
    __shared__ ull s_v[Hn][8];
    __shared__ float s_wm[3];

    int w = blockIdx.x, d = blockIdx.y, h = threadIdx.x;
    int p = d * HWn + h * Wn + w;

    float2 qv = ((const float2*)g_q)[p];
    float2 kv = ((const float2*)g_k)[p];
    s_kx[h] = kv.x; s_ky[h] = kv.y;

    const ulonglong2* gv = (const ulonglong2*)&g_v[p * 8];
    ulonglong2 t0 = gv[0], t1 = gv[1], t2 = gv[2], t3 = gv[3];
    ull myv[8] = { t0.x, t0.y, t1.x, t1.y, t2.x, t2.y, t3.x, t3.y };
    ulonglong2* sv = (ulonglong2*)s_v[h];
    sv[0] = t0; sv[1] = t1; sv[2] = t2; sv[3] = t3;

    float nk = kv.x * kv.x + kv.y * kv.y;
#pragma unroll
    for (int off = 16; off; off >>= 1)
        nk = fmaxf(nk, __shfl_xor_sync(0xffffffffu, nk, off));
    if ((h & 31) == 0) s_wm[h >> 5] = nk;
    __syncthreads();

    float nkm = fmaxf(s_wm[0], fmaxf(s_wm[1], s_wm[2]));
    float m = sqrtf((qv.x * qv.x + qv.y * qv.y) * nkm);   // upper bound on energies

    ull qxx = dup2(qv.x), qyy = dup2(qv.y), mneg = dup2(-m);
    ull s2 = pack2(0.f, 0.f);
    ull acc[8];
#pragma unroll
    for (int i = 0; i < 8; i++) acc[i] = pack2(0.f, 0.f);

#pragma unroll 2
    for (int j = 0; j < Hn; j += 2) {
        ull kx2 = *(const ull*)&s_kx[j];
        ull ky2 = *(const ull*)&s_ky[j];
        ull e2; F2(e2, qyy, ky2, mneg); F2(e2, qxx, kx2, e2);
        float2 ef = unpack2(e2);
        float pa = ex2f(ef.x), pb = ex2f(ef.y);
        ull pp = pack2(pa, pb);
        A2(s2, s2, pp);
        ull pa2 = dup2(pa), pb2 = dup2(pb);
        const ulonglong2* va = (const ulonglong2*)s_v[j];
        const ulonglong2* vb = (const ulonglong2*)s_v[j + 1];
#pragma unroll
        for (int i = 0; i < 4; i++) {
            ulonglong2 ta = va[i], tb = vb[i];
            F2(acc[2 * i],     pa2, ta.x, acc[2 * i]);
            F2(acc[2 * i + 1], pa2, ta.y, acc[2 * i + 1]);
            F2(acc[2 * i],     pb2, tb.x, acc[2 * i]);
            F2(acc[2 * i + 1], pb2, tb.y, acc[2 * i + 1]);
        }
    }

    // remove diagonal contribution (mask): subtract own term
    float eh = fmaf(qv.x, kv.x, qv.y * kv.y) - m;
    float ph = ex2f(eh);
    ull phn = dup2(-ph);
#pragma unroll
    for (int i = 0; i < 8; i++) F2(acc[i], phn, myv[i], acc[i]);

    float2 sf = unpack2(s2);
    g_mH[p] = m;
    g_sH[p] = sf.x + sf.y - ph;
    ulonglong2* op = (ulonglong2*)&g_oH[p * 8];
    op[0] = make_ulonglong2(acc[0], acc[1]);
    op[1] = make_ulonglong2(acc[2], acc[3]);
    op[2] = make_ulonglong2(acc[4], acc[5]);
    op[3] = make_ulonglong2(acc[6], acc[7]);
}

// ---------------------------------------------------------------------------
// Pass B: W-direction partials + joint-softmax combine + residual.
// ---------------------------------------------------------------------------
__global__ __launch_bounds__(Wn) void passB_kernel(const float* __restrict__ xin,
                                                   float* __restrict__ dst,
                                                   const float* __restrict__ gammap)
{
    __shared__ __align__(8) float s_kx[Wn], s_ky[Wn];
    __shared__ ull s_v[Wn][8];
    __shared__ float s_wm[6];

    int h = blockIdx.x, d = blockIdx.y, w = threadIdx.x;
    const float* x = xin ? xin : g_y;
    float*       y = dst ? dst : g_y;

    int p = d * HWn + h * Wn + w;

    float2 qv = ((const float2*)g_q)[p];
    float2 kv = ((const float2*)g_k)[p];
    s_kx[w] = kv.x; s_ky[w] = kv.y;

    const ulonglong2* gv = (const ulonglong2*)&g_v[p * 8];
    ulonglong2 t0 = gv[0], t1 = gv[1], t2 = gv[2], t3 = gv[3];
    ulonglong2* sv = (ulonglong2*)s_v[w];
    sv[0] = t0; sv[1] = t1; sv[2] = t2; sv[3] = t3;

    float nk = kv.x * kv.x + kv.y * kv.y;
#pragma unroll
    for (int off = 16; off; off >>= 1)
        nk = fmaxf(nk, __shfl_xor_sync(0xffffffffu, nk, off));
    if ((w & 31) == 0) s_wm[w >> 5] = nk;
    __syncthreads();

    float nkm = s_wm[0];
#pragma unroll
    for (int i = 1; i < 6; i++) nkm = fmaxf(nkm, s_wm[i]);
    float m = sqrtf((qv.x * qv.x + qv.y * qv.y) * nkm);

    ull qxx = dup2(qv.x), qyy = dup2(qv.y), mneg = dup2(-m);
    ull s2 = pack2(0.f, 0.f);
    ull acc[8];
#pragma unroll
    for (int i = 0; i < 8; i++) acc[i] = pack2(0.f, 0.f);

#pragma unroll 2
    for (int j = 0; j < Wn; j += 2) {
        ull kx2 = *(const ull*)&s_kx[j];
        ull ky2 = *(const ull*)&s_ky[j];
        ull e2; F2(e2, qyy, ky2, mneg); F2(e2, qxx, kx2, e2);
        float2 ef = unpack2(e2);
        float pa = ex2f(ef.x), pb = ex2f(ef.y);
        ull pp = pack2(pa, pb);
        A2(s2, s2, pp);
        ull pa2 = dup2(pa), pb2 = dup2(pb);
        const ulonglong2* va = (const ulonglong2*)s_v[j];
        const ulonglong2* vb = (const ulonglong2*)s_v[j + 1];
#pragma unroll
        for (int i = 0; i < 4; i++) {
            ulonglong2 ta = va[i], tb = vb[i];
            F2(acc[2 * i],     pa2, ta.x, acc[2 * i]);
            F2(acc[2 * i + 1], pa2, ta.y, acc[2 * i + 1]);
            F2(acc[2 * i],     pb2, tb.x, acc[2 * i]);
            F2(acc[2 * i + 1], pb2, tb.y, acc[2 * i + 1]);
        }
    }

    float2 sf = unpack2(s2);
    float sW = sf.x + sf.y;
    float mH = g_mH[p];
    float sH = g_sH[p];
    float mm = fmaxf(m, mH);
    float aW = ex2f(m - mm);
    float aH = ex2f(mH - mm);
    float inv = __fdividef(gammap[0], fmaf(sW, aW, sH * aH));  // gamma folded in
    ull cW2 = dup2(aW * inv), cH2 = dup2(aH * inv);

    const ull* ohp = (const ull*)&g_oH[p * 8];
#pragma unroll
    for (int j = 0; j < 8; j++) {
        ull oh = ohp[j];
        ull r; M2(r, oh, cH2);
        F2(r, acc[j], cW2, r);
        float2 rf = unpack2(r);
        y[(2 * j)     * Pn + p] = x[(2 * j)     * Pn + p] + rf.x;
        y[(2 * j + 1) * Pn + p] = x[(2 * j + 1) * Pn + p] + rf.y;
    }
}

// ---------------------------------------------------------------------------
extern "C" void kernel_launch(void* const* d_in, const int* in_sizes, int n_in,
                              void* d_out, int out_size)
{
    const float* x     = (const float*)d_in[0];
    const float* qw    = (const float*)d_in[1];
    const float* qb    = (const float*)d_in[2];
    const float* kw    = (const float*)d_in[3];
    const float* kb    = (const float*)d_in[4];
    const float* vw    = (const float*)d_in[5];
    const float* vb    = (const float*)d_in[6];
    const float* gamma = (const float*)d_in[7];
    float* out = (float*)d_out;

    dim3 gA(Wn, Dn);
    dim3 gB(Hn, Dn);
    int qkvBlocks = Pn / 256;

    qkv_kernel<<<qkvBlocks, 256>>>(x, qw, qb, kw, kb, vw, vb);
    passA_kernel<<<gA, Hn>>>();
    passB_kernel<<<gB, Wn>>>(x, nullptr, gamma);

    qkv_kernel<<<qkvBlocks, 256>>>(nullptr, qw, qb, kw, kb, vw, vb);
    passA_kernel<<<gA, Hn>>>();
    passB_kernel<<<gB, Wn>>>(nullptr, out, gamma);
}

// round 4
// speedup vs baseline: 1.3597x; 1.1769x over previous
#include <cuda_runtime.h>

#define Dn 24
#define Hn 96
#define Wn 192
#define HWn (Hn * Wn)          // 18432
#define Pn (Dn * HWn)          // 442368

typedef unsigned long long ull;

// Scratch (device globals — allocation forbidden)
__device__ float g_q[Pn * 2];      // [p][2], q pre-scaled by log2(e)
__device__ float g_k[Pn * 2];      // [p][2]
__device__ ull   g_v[Pn * 8];      // [p][8] channel pairs packed as f32x2
__device__ float g_y[Pn * 16];     // intermediate image, [c][p]
__device__ float g_mH[Pn];
__device__ float g_sH[Pn];
__device__ ull   g_oH[Pn * 8];     // unnormalized out_H, channel pairs

// ---- f32x2 helpers -------------------------------------------------------
__device__ __forceinline__ void F2(ull& d, ull a, ull b, ull c) {
    asm("fma.rn.f32x2 %0,%1,%2,%3;" : "=l"(d) : "l"(a), "l"(b), "l"(c));
}
__device__ __forceinline__ void M2(ull& d, ull a, ull b) {
    asm("mul.rn.f32x2 %0,%1,%2;" : "=l"(d) : "l"(a), "l"(b));
}
__device__ __forceinline__ void A2(ull& d, ull a, ull b) {
    asm("add.rn.f32x2 %0,%1,%2;" : "=l"(d) : "l"(a), "l"(b));
}
__device__ __forceinline__ ull pack2(float lo, float hi) {
    ull r; asm("mov.b64 %0,{%1,%2};" : "=l"(r) : "f"(lo), "f"(hi)); return r;
}
__device__ __forceinline__ ull dup2(float v) { return pack2(v, v); }
__device__ __forceinline__ float2 unpack2(ull v) {
    float2 r; asm("mov.b64 {%0,%1},%2;" : "=f"(r.x), "=f"(r.y) : "l"(v)); return r;
}
__device__ __forceinline__ float ex2f(float x) {
    float r; asm("ex2.approx.ftz.f32 %0,%1;" : "=f"(r) : "f"(x)); return r;
}

#define L2E 1.44269504088896340736f

// ---------------------------------------------------------------------------
// QKV projection
// ---------------------------------------------------------------------------
__global__ __launch_bounds__(256) void qkv_kernel(const float* __restrict__ xin,
                           const float* __restrict__ qw, const float* __restrict__ qb,
                           const float* __restrict__ kw, const float* __restrict__ kb,
                           const float* __restrict__ vw, const float* __restrict__ vb)
{
    __shared__ float s_qw[32], s_kw[32], s_qb[2], s_kb[2];
    __shared__ ull s_vw[16][8];   // [c][opair]
    __shared__ ull s_vb[8];
    const float* x = xin ? xin : g_y;

    int t = threadIdx.x;
    if (t < 128) {
        int c = t & 15, j = t >> 4;
        s_vw[c][j] = pack2(vw[(2 * j) * 16 + c], vw[(2 * j + 1) * 16 + c]);
    } else if (t < 160)  s_qw[t - 128] = qw[t - 128];
    else if (t < 192)    s_kw[t - 160] = kw[t - 160];
    else if (t < 194)    s_qb[t - 192] = qb[t - 192];
    else if (t < 196)    s_kb[t - 194] = kb[t - 194];
    else if (t < 204)    s_vb[t - 196] = pack2(vb[2 * (t - 196)], vb[2 * (t - 196) + 1]);
    __syncthreads();

    int p = blockIdx.x * 256 + t;

    float xv[16];
#pragma unroll
    for (int c = 0; c < 16; c++) xv[c] = x[c * Pn + p];

    float q0 = s_qb[0], q1 = s_qb[1], k0 = s_kb[0], k1 = s_kb[1];
#pragma unroll
    for (int c = 0; c < 16; c++) {
        q0 = fmaf(s_qw[c],      xv[c], q0);
        q1 = fmaf(s_qw[16 + c], xv[c], q1);
        k0 = fmaf(s_kw[c],      xv[c], k0);
        k1 = fmaf(s_kw[16 + c], xv[c], k1);
    }
    ((float2*)g_q)[p] = make_float2(q0 * L2E, q1 * L2E);
    ((float2*)g_k)[p] = make_float2(k0, k1);

    ull av[8];
#pragma unroll
    for (int j = 0; j < 8; j++) av[j] = s_vb[j];
#pragma unroll
    for (int c = 0; c < 16; c++) {
        ull xc2 = dup2(xv[c]);
#pragma unroll
        for (int j = 0; j < 8; j++) F2(av[j], s_vw[c][j], xc2, av[j]);
    }
    ulonglong2* vp = (ulonglong2*)&g_v[(size_t)p * 8];
    vp[0] = make_ulonglong2(av[0], av[1]);
    vp[1] = make_ulonglong2(av[2], av[3]);
    vp[2] = make_ulonglong2(av[4], av[5]);
    vp[3] = make_ulonglong2(av[6], av[7]);
}

// ---------------------------------------------------------------------------
// Pass A: H-direction. Block covers 2 columns (w0, w0+1), 96 threads.
// Thread handles 2 query rows of one column; k/v LDS amortized over both.
// ---------------------------------------------------------------------------
__global__ __launch_bounds__(96) void passA_kernel()
{
    __shared__ float s_kx[2][100], s_ky[2][100];   // padded: bank-disjoint columns
    __shared__ ull s_v[2][97][8];                  // padded: stride 6208B
    __shared__ float s_wm[3];

    int d = blockIdx.y;
    int t = threadIdx.x;
    int col = t >= 48;
    int r0  = (t - col * 48) * 2;
    int w   = blockIdx.x * 2 + col;

    int p0 = d * HWn + r0 * Wn + w;
    int p1 = p0 + Wn;

    float2 q0 = ((const float2*)g_q)[p0];
    float2 q1 = ((const float2*)g_q)[p1];
    float2 k0 = ((const float2*)g_k)[p0];
    float2 k1 = ((const float2*)g_k)[p1];
    s_kx[col][r0]     = k0.x;  s_ky[col][r0]     = k0.y;
    s_kx[col][r0 + 1] = k1.x;  s_ky[col][r0 + 1] = k1.y;

    {
        const ulonglong2* gv = (const ulonglong2*)&g_v[(size_t)p0 * 8];
        ulonglong2* sv = (ulonglong2*)s_v[col][r0];
        sv[0] = gv[0]; sv[1] = gv[1]; sv[2] = gv[2]; sv[3] = gv[3];
        gv = (const ulonglong2*)&g_v[(size_t)p1 * 8];
        sv = (ulonglong2*)s_v[col][r0 + 1];
        sv[0] = gv[0]; sv[1] = gv[1]; sv[2] = gv[2]; sv[3] = gv[3];
    }

    float nk = fmaxf(fmaf(k0.x, k0.x, k0.y * k0.y),
                     fmaf(k1.x, k1.x, k1.y * k1.y));
#pragma unroll
    for (int off = 16; off; off >>= 1)
        nk = fmaxf(nk, __shfl_xor_sync(0xffffffffu, nk, off));
    if ((t & 31) == 0) s_wm[t >> 5] = nk;
    __syncthreads();

    float nkm = fmaxf(s_wm[0], fmaxf(s_wm[1], s_wm[2]));
    float m0 = sqrtf(fmaf(q0.x, q0.x, q0.y * q0.y) * nkm);
    float m1 = sqrtf(fmaf(q1.x, q1.x, q1.y * q1.y) * nkm);

    ull qx0 = dup2(q0.x), qy0 = dup2(q0.y), mn0 = dup2(-m0);
    ull qx1 = dup2(q1.x), qy1 = dup2(q1.y), mn1 = dup2(-m1);
    ull s20 = 0, s21 = 0;
    ull acc0[8], acc1[8];
#pragma unroll
    for (int i = 0; i < 8; i++) { acc0[i] = 0; acc1[i] = 0; }

    const float* kxp = s_kx[col];
    const float* kyp = s_ky[col];

    for (int j = 0; j < Hn; j += 2) {
        ull kx2 = *(const ull*)&kxp[j];
        ull ky2 = *(const ull*)&kyp[j];
        ull e0; F2(e0, qy0, ky2, mn0); F2(e0, qx0, kx2, e0);
        ull e1; F2(e1, qy1, ky2, mn1); F2(e1, qx1, kx2, e1);
        float2 f0 = unpack2(e0), f1 = unpack2(e1);
        float pa0 = ex2f(f0.x), pb0 = ex2f(f0.y);
        float pa1 = ex2f(f1.x), pb1 = ex2f(f1.y);
        A2(s20, s20, pack2(pa0, pb0));
        A2(s21, s21, pack2(pa1, pb1));
        ull pa02 = dup2(pa0), pb02 = dup2(pb0);
        ull pa12 = dup2(pa1), pb12 = dup2(pb1);
        const ulonglong2* va = (const ulonglong2*)s_v[col][j];
        const ulonglong2* vb = (const ulonglong2*)s_v[col][j + 1];
#pragma unroll
        for (int i = 0; i < 4; i++) {
            ulonglong2 ta = va[i], tb = vb[i];
            F2(acc0[2 * i],     pa02, ta.x, acc0[2 * i]);
            F2(acc0[2 * i + 1], pa02, ta.y, acc0[2 * i + 1]);
            F2(acc0[2 * i],     pb02, tb.x, acc0[2 * i]);
            F2(acc0[2 * i + 1], pb02, tb.y, acc0[2 * i + 1]);
            F2(acc1[2 * i],     pa12, ta.x, acc1[2 * i]);
            F2(acc1[2 * i + 1], pa12, ta.y, acc1[2 * i + 1]);
            F2(acc1[2 * i],     pb12, tb.x, acc1[2 * i]);
            F2(acc1[2 * i + 1], pb12, tb.y, acc1[2 * i + 1]);
        }
    }

    // remove diagonal contribution for each query (own row)
    float ph0 = ex2f(fmaf(q0.x, k0.x, q0.y * k0.y) - m0);
    float ph1 = ex2f(fmaf(q1.x, k1.x, q1.y * k1.y) - m1);
    ull phn0 = dup2(-ph0), phn1 = dup2(-ph1);
    {
        const ull* mv0 = s_v[col][r0];
        const ull* mv1 = s_v[col][r0 + 1];
#pragma unroll
        for (int i = 0; i < 8; i++) {
            F2(acc0[i], phn0, mv0[i], acc0[i]);
            F2(acc1[i], phn1, mv1[i], acc1[i]);
        }
    }

    float2 sf0 = unpack2(s20), sf1 = unpack2(s21);
    g_mH[p0] = m0;  g_sH[p0] = sf0.x + sf0.y - ph0;
    g_mH[p1] = m1;  g_sH[p1] = sf1.x + sf1.y - ph1;

    ulonglong2* op = (ulonglong2*)&g_oH[(size_t)p0 * 8];
    op[0] = make_ulonglong2(acc0[0], acc0[1]);
    op[1] = make_ulonglong2(acc0[2], acc0[3]);
    op[2] = make_ulonglong2(acc0[4], acc0[5]);
    op[3] = make_ulonglong2(acc0[6], acc0[7]);
    op = (ulonglong2*)&g_oH[(size_t)p1 * 8];
    op[0] = make_ulonglong2(acc1[0], acc1[1]);
    op[1] = make_ulonglong2(acc1[2], acc1[3]);
    op[2] = make_ulonglong2(acc1[4], acc1[5]);   // <-- fixed (was acc1[3])
    op[3] = make_ulonglong2(acc1[6], acc1[7]);
}

// ---------------------------------------------------------------------------
// Pass B: W-direction + combine + residual. Block = (d,h) row, 96 threads,
// thread handles pixels w=2t, 2t+1.
// ---------------------------------------------------------------------------
__global__ __launch_bounds__(96) void passB_kernel(const float* __restrict__ xin,
                                                   float* __restrict__ dst,
                                                   const float* __restrict__ gammap)
{
    __shared__ float s_kx[Wn], s_ky[Wn];
    __shared__ ull s_v[Wn][8];
    __shared__ float s_wm[3];

    int h = blockIdx.x, d = blockIdx.y, t = threadIdx.x;
    const float* x = xin ? xin : g_y;
    float*       y = dst ? dst : g_y;

    int w0 = 2 * t;
    int p0 = d * HWn + h * Wn + w0;
    int p1 = p0 + 1;

    float2 q0 = ((const float2*)g_q)[p0];
    float2 q1 = ((const float2*)g_q)[p1];
    float2 k0 = ((const float2*)g_k)[p0];
    float2 k1 = ((const float2*)g_k)[p1];
    s_kx[w0] = k0.x;  s_ky[w0] = k0.y;
    s_kx[w0 + 1] = k1.x;  s_ky[w0 + 1] = k1.y;

    {
        const ulonglong2* gv = (const ulonglong2*)&g_v[(size_t)p0 * 8];
        ulonglong2* sv = (ulonglong2*)s_v[w0];
        sv[0] = gv[0]; sv[1] = gv[1]; sv[2] = gv[2]; sv[3] = gv[3];
        gv = (const ulonglong2*)&g_v[(size_t)p1 * 8];
        sv = (ulonglong2*)s_v[w0 + 1];
        sv[0] = gv[0]; sv[1] = gv[1]; sv[2] = gv[2]; sv[3] = gv[3];
    }

    float nk = fmaxf(fmaf(k0.x, k0.x, k0.y * k0.y),
                     fmaf(k1.x, k1.x, k1.y * k1.y));
#pragma unroll
    for (int off = 16; off; off >>= 1)
        nk = fmaxf(nk, __shfl_xor_sync(0xffffffffu, nk, off));
    if ((t & 31) == 0) s_wm[t >> 5] = nk;
    __syncthreads();

    float nkm = fmaxf(s_wm[0], fmaxf(s_wm[1], s_wm[2]));
    float m0 = sqrtf(fmaf(q0.x, q0.x, q0.y * q0.y) * nkm);
    float m1 = sqrtf(fmaf(q1.x, q1.x, q1.y * q1.y) * nkm);

    ull qx0 = dup2(q0.x), qy0 = dup2(q0.y), mn0 = dup2(-m0);
    ull qx1 = dup2(q1.x), qy1 = dup2(q1.y), mn1 = dup2(-m1);
    ull s20 = 0, s21 = 0;
    ull acc0[8], acc1[8];
#pragma unroll
    for (int i = 0; i < 8; i++) { acc0[i] = 0; acc1[i] = 0; }

    for (int j = 0; j < Wn; j += 2) {
        ull kx2 = *(const ull*)&s_kx[j];
        ull ky2 = *(const ull*)&s_ky[j];
        ull e0; F2(e0, qy0, ky2, mn0); F2(e0, qx0, kx2, e0);
        ull e1; F2(e1, qy1, ky2, mn1); F2(e1, qx1, kx2, e1);
        float2 f0 = unpack2(e0), f1 = unpack2(e1);
        float pa0 = ex2f(f0.x), pb0 = ex2f(f0.y);
        float pa1 = ex2f(f1.x), pb1 = ex2f(f1.y);
        A2(s20, s20, pack2(pa0, pb0));
        A2(s21, s21, pack2(pa1, pb1));
        ull pa02 = dup2(pa0), pb02 = dup2(pb0);
        ull pa12 = dup2(pa1), pb12 = dup2(pb1);
        const ulonglong2* va = (const ulonglong2*)s_v[j];
        const ulonglong2* vb = (const ulonglong2*)s_v[j + 1];
#pragma unroll
        for (int i = 0; i < 4; i++) {
            ulonglong2 ta = va[i], tb = vb[i];
            F2(acc0[2 * i],     pa02, ta.x, acc0[2 * i]);
            F2(acc0[2 * i + 1], pa02, ta.y, acc0[2 * i + 1]);
            F2(acc0[2 * i],     pb02, tb.x, acc0[2 * i]);
            F2(acc0[2 * i + 1], pb02, tb.y, acc0[2 * i + 1]);
            F2(acc1[2 * i],     pa12, ta.x, acc1[2 * i]);
            F2(acc1[2 * i + 1], pa12, ta.y, acc1[2 * i + 1]);
            F2(acc1[2 * i],     pb12, tb.x, acc1[2 * i]);
            F2(acc1[2 * i + 1], pb12, tb.y, acc1[2 * i + 1]);
        }
    }

    float2 sf0 = unpack2(s20), sf1 = unpack2(s21);
    float sW0 = sf0.x + sf0.y, sW1 = sf1.x + sf1.y;

    float2 mH2 = *(const float2*)&g_mH[p0];
    float2 sH2 = *(const float2*)&g_sH[p0];
    float gamma = gammap[0];

    float mm0 = fmaxf(m0, mH2.x);
    float aW0 = ex2f(m0 - mm0), aH0 = ex2f(mH2.x - mm0);
    float inv0 = __fdividef(gamma, fmaf(sW0, aW0, sH2.x * aH0));
    ull cW0 = dup2(aW0 * inv0), cH0 = dup2(aH0 * inv0);

    float mm1 = fmaxf(m1, mH2.y);
    float aW1 = ex2f(m1 - mm1), aH1 = ex2f(mH2.y - mm1);
    float inv1 = __fdividef(gamma, fmaf(sW1, aW1, sH2.y * aH1));
    ull cW1 = dup2(aW1 * inv1), cH1 = dup2(aH1 * inv1);

    const ull* oh0 = (const ull*)&g_oH[(size_t)p0 * 8];
    const ull* oh1 = (const ull*)&g_oH[(size_t)p1 * 8];
#pragma unroll
    for (int j = 0; j < 8; j++) {
        ull r0v; M2(r0v, oh0[j], cH0); F2(r0v, acc0[j], cW0, r0v);
        ull r1v; M2(r1v, oh1[j], cH1); F2(r1v, acc1[j], cW1, r1v);
        float2 ra = unpack2(r0v);   // pixel0: channels 2j, 2j+1
        float2 rb = unpack2(r1v);   // pixel1: channels 2j, 2j+1
        float2 xlo = *(const float2*)&x[(2 * j) * Pn + p0];
        float2 xhi = *(const float2*)&x[(2 * j + 1) * Pn + p0];
        *(float2*)&y[(2 * j)     * Pn + p0] = make_float2(xlo.x + ra.x, xlo.y + rb.x);
        *(float2*)&y[(2 * j + 1) * Pn + p0] = make_float2(xhi.x + ra.y, xhi.y + rb.y);
    }
}

// ---------------------------------------------------------------------------
extern "C" void kernel_launch(void* const* d_in, const int* in_sizes, int n_in,
                              void* d_out, int out_size)
{
    const float* x     = (const float*)d_in[0];
    const float* qw    = (const float*)d_in[1];
    const float* qb    = (const float*)d_in[2];
    const float* kw    = (const float*)d_in[3];
    const float* kb    = (const float*)d_in[4];
    const float* vw    = (const float*)d_in[5];
    const float* vb    = (const float*)d_in[6];
    const float* gamma = (const float*)d_in[7];
    float* out = (float*)d_out;

    dim3 gA(Wn / 2, Dn);   // 96 x 24 blocks, 96 threads (2 columns/block)
    dim3 gB(Hn, Dn);       // 96 x 24 blocks, 96 threads (2 pixels/thread)
    int qkvBlocks = Pn / 256;

    qkv_kernel<<<qkvBlocks, 256>>>(x, qw, qb, kw, kb, vw, vb);
    passA_kernel<<<gA, 96>>>();
    passB_kernel<<<gB, 96>>>(x, nullptr, gamma);

    qkv_kernel<<<qkvBlocks, 256>>>(nullptr, qw, qb, kw, kb, vw, vb);
    passA_kernel<<<gA, 96>>>();
    passB_kernel<<<gB, 96>>>(nullptr, out, gamma);
}

// round 5
// speedup vs baseline: 1.4458x; 1.0633x over previous
#include <cuda_runtime.h>

#define Dn 24
#define Hn 96
#define Wn 192
#define HWn (Hn * Wn)          // 18432
#define Pn (Dn * HWn)          // 442368

typedef unsigned long long ull;

// Scratch (device globals — allocation forbidden)
__device__ float g_q[Pn * 2];      // [p][2], q pre-scaled by log2(e)
__device__ float g_k[Pn * 2];      // [p][2]
__device__ ull   g_v[Pn * 8];      // [p][8] channel pairs packed as f32x2
__device__ float g_y[Pn * 16];     // intermediate image, [c][p]
__device__ float g_sH[Pn];
__device__ ull   g_oH[Pn * 8];     // unnormalized out_H, channel pairs

// ---- f32x2 helpers -------------------------------------------------------
__device__ __forceinline__ void F2(ull& d, ull a, ull b, ull c) {
    asm("fma.rn.f32x2 %0,%1,%2,%3;" : "=l"(d) : "l"(a), "l"(b), "l"(c));
}
__device__ __forceinline__ void M2(ull& d, ull a, ull b) {
    asm("mul.rn.f32x2 %0,%1,%2;" : "=l"(d) : "l"(a), "l"(b));
}
__device__ __forceinline__ void A2(ull& d, ull a, ull b) {
    asm("add.rn.f32x2 %0,%1,%2;" : "=l"(d) : "l"(a), "l"(b));
}
__device__ __forceinline__ ull pack2(float lo, float hi) {
    ull r; asm("mov.b64 %0,{%1,%2};" : "=l"(r) : "f"(lo), "f"(hi)); return r;
}
__device__ __forceinline__ ull dup2(float v) { return pack2(v, v); }
__device__ __forceinline__ float2 unpack2(ull v) {
    float2 r; asm("mov.b64 {%0,%1},%2;" : "=f"(r.x), "=f"(r.y) : "l"(v)); return r;
}
__device__ __forceinline__ float ex2f(float x) {
    float r; asm("ex2.approx.ftz.f32 %0,%1;" : "=f"(r) : "f"(x)); return r;
}

#define L2E 1.44269504088896340736f

// ---------------------------------------------------------------------------
// QKV projection
// ---------------------------------------------------------------------------
__global__ __launch_bounds__(256) void qkv_kernel(const float* __restrict__ xin,
                           const float* __restrict__ qw, const float* __restrict__ qb,
                           const float* __restrict__ kw, const float* __restrict__ kb,
                           const float* __restrict__ vw, const float* __restrict__ vb)
{
    __shared__ float s_qw[32], s_kw[32], s_qb[2], s_kb[2];
    __shared__ ull s_vw[16][8];
    __shared__ ull s_vb[8];
    const float* x = xin ? xin : g_y;

    int t = threadIdx.x;
    if (t < 128) {
        int c = t & 15, j = t >> 4;
        s_vw[c][j] = pack2(vw[(2 * j) * 16 + c], vw[(2 * j + 1) * 16 + c]);
    } else if (t < 160)  s_qw[t - 128] = qw[t - 128];
    else if (t < 192)    s_kw[t - 160] = kw[t - 160];
    else if (t < 194)    s_qb[t - 192] = qb[t - 192];
    else if (t < 196)    s_kb[t - 194] = kb[t - 194];
    else if (t < 204)    s_vb[t - 196] = pack2(vb[2 * (t - 196)], vb[2 * (t - 196) + 1]);
    __syncthreads();

    int p = blockIdx.x * 256 + t;

    float xv[16];
#pragma unroll
    for (int c = 0; c < 16; c++) xv[c] = x[c * Pn + p];

    float q0 = s_qb[0], q1 = s_qb[1], k0 = s_kb[0], k1 = s_kb[1];
#pragma unroll
    for (int c = 0; c < 16; c++) {
        q0 = fmaf(s_qw[c],      xv[c], q0);
        q1 = fmaf(s_qw[16 + c], xv[c], q1);
        k0 = fmaf(s_kw[c],      xv[c], k0);
        k1 = fmaf(s_kw[16 + c], xv[c], k1);
    }
    ((float2*)g_q)[p] = make_float2(q0 * L2E, q1 * L2E);
    ((float2*)g_k)[p] = make_float2(k0, k1);

    ull av[8];
#pragma unroll
    for (int j = 0; j < 8; j++) av[j] = s_vb[j];
#pragma unroll
    for (int c = 0; c < 16; c++) {
        ull xc2 = dup2(xv[c]);
#pragma unroll
        for (int j = 0; j < 8; j++) F2(av[j], s_vw[c][j], xc2, av[j]);
    }
    ulonglong2* vp = (ulonglong2*)&g_v[(size_t)p * 8];
    vp[0] = make_ulonglong2(av[0], av[1]);
    vp[1] = make_ulonglong2(av[2], av[3]);
    vp[2] = make_ulonglong2(av[4], av[5]);
    vp[3] = make_ulonglong2(av[6], av[7]);
}

// ---------------------------------------------------------------------------
// Pass A: H-direction. Block = 4 columns, 96 threads, 4 query rows/thread.
// No softmax shift (energies are O(1)); diagonal removed by subtraction.
// ---------------------------------------------------------------------------
__global__ __launch_bounds__(96) void passA_kernel()
{
    __shared__ float s_kx[4][96], s_ky[4][96];
    __shared__ ull s_v[4][96][8];

    int d = blockIdx.y;
    int t = threadIdx.x;
    int col = t / 24;              // 0..3
    int r0  = (t % 24) * 4;        // 0,4,...,92
    int w4  = blockIdx.x * 4;
    int w   = w4 + col;

    int pbase = d * HWn + w;

    // cooperative, conflict-free v fill: 4 cols x 96 rows x 8 pairs
#pragma unroll
    for (int cc = 0; cc < 4; cc++) {
#pragma unroll
        for (int k2 = 0; k2 < 8; k2++) {
            int idx = t + k2 * 96;           // 0..767
            int row = idx >> 3, pair = idx & 7;
            s_v[cc][row][pair] = g_v[(size_t)(pbase + row * Wn + cc - col) * 8 + pair + (size_t)col * 0];
        }
    }
    // NOTE: the expression above must use column cc, not col; rewritten below
    // (kept simple: recompute correctly)
    __syncthreads();   // ensure no one reads garbage before overwrite below
#pragma unroll
    for (int cc = 0; cc < 4; cc++) {
#pragma unroll
        for (int k2 = 0; k2 < 8; k2++) {
            int idx = t + k2 * 96;
            int row = idx >> 3, pair = idx & 7;
            int p = d * HWn + row * Wn + w4 + cc;
            s_v[cc][row][pair] = g_v[(size_t)p * 8 + pair];
        }
    }

    // q/k for this thread's 4 query rows; k also into shared
    float2 q[4], k[4];
#pragma unroll
    for (int i = 0; i < 4; i++) {
        int p = pbase + (r0 + i) * Wn;
        q[i] = ((const float2*)g_q)[p];
        k[i] = ((const float2*)g_k)[p];
        s_kx[col][r0 + i] = k[i].x;
        s_ky[col][r0 + i] = k[i].y;
    }
    __syncthreads();

    ull qx[4], qy[4];
#pragma unroll
    for (int i = 0; i < 4; i++) { qx[i] = dup2(q[i].x); qy[i] = dup2(q[i].y); }

    ull s2[4] = {0, 0, 0, 0};
    ull acc[4][8];
#pragma unroll
    for (int i = 0; i < 4; i++)
#pragma unroll
        for (int j = 0; j < 8; j++) acc[i][j] = 0;

    const float* kxp = s_kx[col];
    const float* kyp = s_ky[col];

#pragma unroll 2
    for (int j = 0; j < Hn; j += 2) {
        ull kx2 = *(const ull*)&kxp[j];
        ull ky2 = *(const ull*)&kyp[j];
        ull pa2[4], pb2[4];
#pragma unroll
        for (int i = 0; i < 4; i++) {
            ull e; M2(e, qx[i], kx2); F2(e, qy[i], ky2, e);
            float2 ef = unpack2(e);
            float pa = ex2f(ef.x), pb = ex2f(ef.y);
            A2(s2[i], s2[i], pack2(pa, pb));
            pa2[i] = dup2(pa); pb2[i] = dup2(pb);
        }
        const ulonglong2* va = (const ulonglong2*)s_v[col][j];
        const ulonglong2* vb = (const ulonglong2*)s_v[col][j + 1];
#pragma unroll
        for (int ii = 0; ii < 4; ii++) {
            ulonglong2 ta = va[ii], tb = vb[ii];
#pragma unroll
            for (int i = 0; i < 4; i++) {
                F2(acc[i][2 * ii],     pa2[i], ta.x, acc[i][2 * ii]);
                F2(acc[i][2 * ii + 1], pa2[i], ta.y, acc[i][2 * ii + 1]);
                F2(acc[i][2 * ii],     pb2[i], tb.x, acc[i][2 * ii]);
                F2(acc[i][2 * ii + 1], pb2[i], tb.y, acc[i][2 * ii + 1]);
            }
        }
    }

    // per query: remove diagonal term, write sH and unnormalized oH
#pragma unroll
    for (int i = 0; i < 4; i++) {
        int p = pbase + (r0 + i) * Wn;
        float ph = ex2f(fmaf(q[i].x, k[i].x, q[i].y * k[i].y));
        ull phn = dup2(-ph);
        const ull* mv = s_v[col][r0 + i];
        ull o[8];
#pragma unroll
        for (int jj = 0; jj < 8; jj++) { o[jj] = acc[i][jj]; F2(o[jj], phn, mv[jj], o[jj]); }
        float2 sf = unpack2(s2[i]);
        g_sH[p] = sf.x + sf.y - ph;
        ulonglong2* op = (ulonglong2*)&g_oH[(size_t)p * 8];
        op[0] = make_ulonglong2(o[0], o[1]);
        op[1] = make_ulonglong2(o[2], o[3]);
        op[2] = make_ulonglong2(o[4], o[5]);
        op[3] = make_ulonglong2(o[6], o[7]);
    }
}

// ---------------------------------------------------------------------------
// Pass B: W-direction + combine + residual. Block = 2 rows, 96 threads,
// thread handles 4 consecutive w of one row.
// ---------------------------------------------------------------------------
__global__ __launch_bounds__(96) void passB_kernel(const float* __restrict__ xin,
                                                   float* __restrict__ dst,
                                                   const float* __restrict__ gammap)
{
    __shared__ float s_kx[2][192], s_ky[2][192];
    __shared__ ull s_v[2][192][8];

    int d = blockIdx.y;
    int t = threadIdx.x;
    int row = t / 48;              // 0..1
    int w0  = (t % 48) * 4;        // 0,4,...,188
    int h   = blockIdx.x * 2 + row;
    const float* x = xin ? xin : g_y;
    float*       y = dst ? dst : g_y;

    // cooperative conflict-free v fill: 2 rows x 192 w x 8 pairs
#pragma unroll
    for (int rr = 0; rr < 2; rr++) {
        int hh = blockIdx.x * 2 + rr;
#pragma unroll
        for (int k2 = 0; k2 < 16; k2++) {
            int idx = t + k2 * 96;           // 0..1535
            int ww = idx >> 3, pair = idx & 7;
            int p = d * HWn + hh * Wn + ww;
            s_v[rr][ww][pair] = g_v[(size_t)p * 8 + pair];
        }
    }

    int p0 = d * HWn + h * Wn + w0;
    float2 q[4], k[4];
#pragma unroll
    for (int i = 0; i < 4; i++) {
        q[i] = ((const float2*)g_q)[p0 + i];
        k[i] = ((const float2*)g_k)[p0 + i];
        s_kx[row][w0 + i] = k[i].x;
        s_ky[row][w0 + i] = k[i].y;
    }
    __syncthreads();

    ull qx[4], qy[4];
#pragma unroll
    for (int i = 0; i < 4; i++) { qx[i] = dup2(q[i].x); qy[i] = dup2(q[i].y); }

    ull s2[4] = {0, 0, 0, 0};
    ull acc[4][8];
#pragma unroll
    for (int i = 0; i < 4; i++)
#pragma unroll
        for (int j = 0; j < 8; j++) acc[i][j] = 0;

    const float* kxp = s_kx[row];
    const float* kyp = s_ky[row];

#pragma unroll 2
    for (int j = 0; j < Wn; j += 2) {
        ull kx2 = *(const ull*)&kxp[j];
        ull ky2 = *(const ull*)&kyp[j];
        ull pa2[4], pb2[4];
#pragma unroll
        for (int i = 0; i < 4; i++) {
            ull e; M2(e, qx[i], kx2); F2(e, qy[i], ky2, e);
            float2 ef = unpack2(e);
            float pa = ex2f(ef.x), pb = ex2f(ef.y);
            A2(s2[i], s2[i], pack2(pa, pb));
            pa2[i] = dup2(pa); pb2[i] = dup2(pb);
        }
        const ulonglong2* va = (const ulonglong2*)s_v[row][j];
        const ulonglong2* vb = (const ulonglong2*)s_v[row][j + 1];
#pragma unroll
        for (int ii = 0; ii < 4; ii++) {
            ulonglong2 ta = va[ii], tb = vb[ii];
#pragma unroll
            for (int i = 0; i < 4; i++) {
                F2(acc[i][2 * ii],     pa2[i], ta.x, acc[i][2 * ii]);
                F2(acc[i][2 * ii + 1], pa2[i], ta.y, acc[i][2 * ii + 1]);
                F2(acc[i][2 * ii],     pb2[i], tb.x, acc[i][2 * ii]);
                F2(acc[i][2 * ii + 1], pb2[i], tb.y, acc[i][2 * ii + 1]);
            }
        }
    }

    // combine: Z = sW + sH (no shift anywhere), out = (oW + oH)/Z, residual
    float gamma = gammap[0];
    float4 sH4 = *(const float4*)&g_sH[p0];
    float sH[4] = { sH4.x, sH4.y, sH4.z, sH4.w };
    ull cinv[4];
#pragma unroll
    for (int i = 0; i < 4; i++) {
        float2 sf = unpack2(s2[i]);
        cinv[i] = dup2(__fdividef(gamma, sf.x + sf.y + sH[i]));
    }

#pragma unroll
    for (int j = 0; j < 8; j++) {          // channel pair (2j, 2j+1)
        float2 r[4];
#pragma unroll
        for (int i = 0; i < 4; i++) {
            ull oh = g_oH[(size_t)(p0 + i) * 8 + j];
            ull v; A2(v, acc[i][j], oh);
            M2(v, v, cinv[i]);
            r[i] = unpack2(v);
        }
        float4 xlo = *(const float4*)&x[(2 * j) * Pn + p0];
        float4 xhi = *(const float4*)&x[(2 * j + 1) * Pn + p0];
        *(float4*)&y[(2 * j) * Pn + p0] =
            make_float4(xlo.x + r[0].x, xlo.y + r[1].x, xlo.z + r[2].x, xlo.w + r[3].x);
        *(float4*)&y[(2 * j + 1) * Pn + p0] =
            make_float4(xhi.x + r[0].y, xhi.y + r[1].y, xhi.z + r[2].y, xhi.w + r[3].y);
    }
}

// ---------------------------------------------------------------------------
extern "C" void kernel_launch(void* const* d_in, const int* in_sizes, int n_in,
                              void* d_out, int out_size)
{
    const float* x     = (const float*)d_in[0];
    const float* qw    = (const float*)d_in[1];
    const float* qb    = (const float*)d_in[2];
    const float* kw    = (const float*)d_in[3];
    const float* kb    = (const float*)d_in[4];
    const float* vw    = (const float*)d_in[5];
    const float* vb    = (const float*)d_in[6];
    const float* gamma = (const float*)d_in[7];
    float* out = (float*)d_out;

    dim3 gA(Wn / 4, Dn);   // 48 x 24 blocks, 96 threads (4 columns/block)
    dim3 gB(Hn / 2, Dn);   // 48 x 24 blocks, 96 threads (2 rows/block)
    int qkvBlocks = Pn / 256;

    qkv_kernel<<<qkvBlocks, 256>>>(x, qw, qb, kw, kb, vw, vb);
    passA_kernel<<<gA, 96>>>();
    passB_kernel<<<gB, 96>>>(x, nullptr, gamma);

    qkv_kernel<<<qkvBlocks, 256>>>(nullptr, qw, qb, kw, kb, vw, vb);
    passA_kernel<<<gA, 96>>>();
    passB_kernel<<<gB, 96>>>(nullptr, out, gamma);
}

// round 6
// speedup vs baseline: 2.4500x; 1.6946x over previous
#include <cuda_runtime.h>

#define Dn 24
#define Hn 96
#define Wn 192
#define HWn (Hn * Wn)          // 18432
#define Pn (Dn * HWn)          // 442368

typedef unsigned long long ull;
typedef unsigned int uint;

// Scratch (device globals — allocation forbidden)
__device__ float g_q[Pn * 2];      // [p][2], q pre-scaled by log2(e)
__device__ float g_k[Pn * 2];      // [p][2]
__device__ ull   g_v[Pn * 8];      // [p][8] channel pairs packed as 2xf32
__device__ float g_y[Pn * 16];     // intermediate image, [c][p]
__device__ float g_sH[Pn];
__device__ ull   g_oH[Pn * 8];     // unnormalized out_H, channel pairs

// ---- helpers ---------------------------------------------------------------
__device__ __forceinline__ void F2(ull& d, ull a, ull b, ull c) {
    asm("fma.rn.f32x2 %0,%1,%2,%3;" : "=l"(d) : "l"(a), "l"(b), "l"(c));
}
__device__ __forceinline__ ull pack2(float lo, float hi) {
    ull r; asm("mov.b64 %0,{%1,%2};" : "=l"(r) : "f"(lo), "f"(hi)); return r;
}
__device__ __forceinline__ ull dup2(float v) { return pack2(v, v); }
__device__ __forceinline__ float2 unpack2(ull v) {
    float2 r; asm("mov.b64 {%0,%1},%2;" : "=f"(r.x), "=f"(r.y) : "l"(v)); return r;
}
__device__ __forceinline__ float ex2f(float x) {
    float r; asm("ex2.approx.ftz.f32 %0,%1;" : "=f"(r) : "f"(x)); return r;
}
__device__ __forceinline__ uint tf32c(float f) {
    uint u; asm("cvt.rna.tf32.f32 %0,%1;" : "=r"(u) : "f"(f)); return u;
}
__device__ __forceinline__ void mma8(float& d0, float& d1, float& d2, float& d3,
                                     uint a0, uint a1, uint a2, uint a3,
                                     uint b0, uint b1) {
    asm("mma.sync.aligned.m16n8k8.row.col.f32.tf32.tf32.f32 "
        "{%0,%1,%2,%3},{%4,%5,%6,%7},{%8,%9},{%0,%1,%2,%3};"
        : "+f"(d0), "+f"(d1), "+f"(d2), "+f"(d3)
        : "r"(a0), "r"(a1), "r"(a2), "r"(a3), "r"(b0), "r"(b1));
}

#define L2E 1.44269504088896340736f

// ---------------------------------------------------------------------------
// QKV projection (unchanged, known-good)
// ---------------------------------------------------------------------------
__global__ __launch_bounds__(256) void qkv_kernel(const float* __restrict__ xin,
                           const float* __restrict__ qw, const float* __restrict__ qb,
                           const float* __restrict__ kw, const float* __restrict__ kb,
                           const float* __restrict__ vw, const float* __restrict__ vb)
{
    __shared__ float s_qw[32], s_kw[32], s_qb[2], s_kb[2];
    __shared__ ull s_vw[16][8];
    __shared__ ull s_vb[8];
    const float* x = xin ? xin : g_y;

    int t = threadIdx.x;
    if (t < 128) {
        int c = t & 15, j = t >> 4;
        s_vw[c][j] = pack2(vw[(2 * j) * 16 + c], vw[(2 * j + 1) * 16 + c]);
    } else if (t < 160)  s_qw[t - 128] = qw[t - 128];
    else if (t < 192)    s_kw[t - 160] = kw[t - 160];
    else if (t < 194)    s_qb[t - 192] = qb[t - 192];
    else if (t < 196)    s_kb[t - 194] = kb[t - 194];
    else if (t < 204)    s_vb[t - 196] = pack2(vb[2 * (t - 196)], vb[2 * (t - 196) + 1]);
    __syncthreads();

    int p = blockIdx.x * 256 + t;

    float xv[16];
#pragma unroll
    for (int c = 0; c < 16; c++) xv[c] = x[c * Pn + p];

    float q0 = s_qb[0], q1 = s_qb[1], k0 = s_kb[0], k1 = s_kb[1];
#pragma unroll
    for (int c = 0; c < 16; c++) {
        q0 = fmaf(s_qw[c],      xv[c], q0);
        q1 = fmaf(s_qw[16 + c], xv[c], q1);
        k0 = fmaf(s_kw[c],      xv[c], k0);
        k1 = fmaf(s_kw[16 + c], xv[c], k1);
    }
    ((float2*)g_q)[p] = make_float2(q0 * L2E, q1 * L2E);
    ((float2*)g_k)[p] = make_float2(k0, k1);

    ull av[8];
#pragma unroll
    for (int j = 0; j < 8; j++) av[j] = s_vb[j];
#pragma unroll
    for (int c = 0; c < 16; c++) {
        ull xc2 = dup2(xv[c]);
#pragma unroll
        for (int j = 0; j < 8; j++) F2(av[j], s_vw[c][j], xc2, av[j]);
    }
    ulonglong2* vp = (ulonglong2*)&g_v[(size_t)p * 8];
    vp[0] = make_ulonglong2(av[0], av[1]);
    vp[1] = make_ulonglong2(av[2], av[3]);
    vp[2] = make_ulonglong2(av[4], av[5]);
    vp[3] = make_ulonglong2(av[6], av[7]);
}

// ---------------------------------------------------------------------------
// Pass A (MMA): one column line per block. 6 warps x 16 queries = 96.
// P computed scalar in A-fragment layout; PV via tf32 mma; diag masked.
// ---------------------------------------------------------------------------
__global__ __launch_bounds__(192) void passA_kernel()
{
    __shared__ float2 s_q[96], s_k[96];
    __shared__ uint sV[96 * 24];    // tf32 V, row stride 24 (conflict-free)

    int d = blockIdx.y, w = blockIdx.x, t = threadIdx.x;
    int lineBase = d * HWn + w;               // p = lineBase + h*Wn

    if (t < 96) {
        int p = lineBase + t * Wn;
        s_q[t] = ((const float2*)g_q)[p];
        s_k[t] = ((const float2*)g_k)[p];
    }
    {
        int row = t >> 1, half = t & 1;
        int p = lineBase + row * Wn;
        const ulonglong2* gv = (const ulonglong2*)&g_v[(size_t)p * 8 + half * 4];
        ulonglong2 u0 = gv[0], u1 = gv[1];
        uint* dst = &sV[row * 24 + half * 8];
        float2 f;
        f = unpack2(u0.x); dst[0] = tf32c(f.x); dst[1] = tf32c(f.y);
        f = unpack2(u0.y); dst[2] = tf32c(f.x); dst[3] = tf32c(f.y);
        f = unpack2(u1.x); dst[4] = tf32c(f.x); dst[5] = tf32c(f.y);
        f = unpack2(u1.y); dst[6] = tf32c(f.x); dst[7] = tf32c(f.y);
    }
    __syncthreads();

    int warp = t >> 5, lane = t & 31, g = lane >> 2, tig = lane & 3;
    int r0 = warp * 16 + g, r1 = r0 + 8;
    float2 q0 = s_q[r0], q1 = s_q[r1];

    float D0[4] = {0, 0, 0, 0};   // channels nt0: 2tig, 2tig+1
    float D1[4] = {0, 0, 0, 0};   // channels nt1
    float sum0 = 0.f, sum1 = 0.f;

#pragma unroll 2
    for (int kt = 0; kt < 12; kt++) {
        int c0 = kt * 8 + tig, c1 = c0 + 4;
        float2 ka = s_k[c0], kb = s_k[c1];
        float e00 = fmaf(q0.y, ka.y, q0.x * ka.x);
        float e01 = fmaf(q0.y, kb.y, q0.x * kb.x);
        float e10 = fmaf(q1.y, ka.y, q1.x * ka.x);
        float e11 = fmaf(q1.y, kb.y, q1.x * kb.x);
        float p00 = (c0 == r0) ? 0.f : ex2f(e00);
        float p01 = (c1 == r0) ? 0.f : ex2f(e01);
        float p10 = (c0 == r1) ? 0.f : ex2f(e10);
        float p11 = (c1 == r1) ? 0.f : ex2f(e11);
        sum0 += p00 + p01;
        sum1 += p10 + p11;
        uint a0 = tf32c(p00), a1 = tf32c(p10), a2 = tf32c(p01), a3 = tf32c(p11);
        const uint* vb0 = &sV[c0 * 24];
        const uint* vb1 = &sV[c1 * 24];
        mma8(D0[0], D0[1], D0[2], D0[3], a0, a1, a2, a3, vb0[g],     vb1[g]);
        mma8(D1[0], D1[1], D1[2], D1[3], a0, a1, a2, a3, vb0[8 + g], vb1[8 + g]);
    }

    sum0 += __shfl_xor_sync(0xffffffffu, sum0, 1);
    sum0 += __shfl_xor_sync(0xffffffffu, sum0, 2);
    sum1 += __shfl_xor_sync(0xffffffffu, sum1, 1);
    sum1 += __shfl_xor_sync(0xffffffffu, sum1, 2);

    int p0 = lineBase + r0 * Wn, p1 = lineBase + r1 * Wn;
    if (tig == 0) { g_sH[p0] = sum0; g_sH[p1] = sum1; }
    g_oH[(size_t)p0 * 8 + tig]     = pack2(D0[0], D0[1]);
    g_oH[(size_t)p1 * 8 + tig]     = pack2(D0[2], D0[3]);
    g_oH[(size_t)p0 * 8 + 4 + tig] = pack2(D1[0], D1[1]);
    g_oH[(size_t)p1 * 8 + 4 + tig] = pack2(D1[2], D1[3]);
}

// ---------------------------------------------------------------------------
// Pass B (MMA): one row line per block. 12 warps x 16 queries = 192.
// Combine with H partials + residual in the epilogue.
// ---------------------------------------------------------------------------
__global__ __launch_bounds__(384) void passB_kernel(const float* __restrict__ xin,
                                                    float* __restrict__ dst,
                                                    const float* __restrict__ gammap)
{
    __shared__ float2 s_q[192], s_k[192];
    __shared__ uint sV[192 * 24];

    int d = blockIdx.y, h = blockIdx.x, t = threadIdx.x;
    int lineBase = d * HWn + h * Wn;          // p = lineBase + w
    const float* x = xin ? xin : g_y;
    float*       y = dst ? dst : g_y;

    if (t < 192) {
        int p = lineBase + t;
        s_q[t] = ((const float2*)g_q)[p];
        s_k[t] = ((const float2*)g_k)[p];
    }
#pragma unroll
    for (int kk = 0; kk < 4; kk++) {
        int f = t + kk * 384;                  // 0..1535
        int row = f >> 3, pair = f & 7;
        float2 fv = unpack2(g_v[(size_t)(lineBase + row) * 8 + pair]);
        sV[row * 24 + pair * 2]     = tf32c(fv.x);
        sV[row * 24 + pair * 2 + 1] = tf32c(fv.y);
    }
    __syncthreads();

    int warp = t >> 5, lane = t & 31, g = lane >> 2, tig = lane & 3;
    int r0 = warp * 16 + g, r1 = r0 + 8;
    float2 q0 = s_q[r0], q1 = s_q[r1];

    float D0[4] = {0, 0, 0, 0};
    float D1[4] = {0, 0, 0, 0};
    float sum0 = 0.f, sum1 = 0.f;

#pragma unroll 2
    for (int kt = 0; kt < 24; kt++) {
        int c0 = kt * 8 + tig, c1 = c0 + 4;
        float2 ka = s_k[c0], kb = s_k[c1];
        float e00 = fmaf(q0.y, ka.y, q0.x * ka.x);
        float e01 = fmaf(q0.y, kb.y, q0.x * kb.x);
        float e10 = fmaf(q1.y, ka.y, q1.x * ka.x);
        float e11 = fmaf(q1.y, kb.y, q1.x * kb.x);
        float p00 = ex2f(e00);
        float p01 = ex2f(e01);
        float p10 = ex2f(e10);
        float p11 = ex2f(e11);
        sum0 += p00 + p01;
        sum1 += p10 + p11;
        uint a0 = tf32c(p00), a1 = tf32c(p10), a2 = tf32c(p01), a3 = tf32c(p11);
        const uint* vb0 = &sV[c0 * 24];
        const uint* vb1 = &sV[c1 * 24];
        mma8(D0[0], D0[1], D0[2], D0[3], a0, a1, a2, a3, vb0[g],     vb1[g]);
        mma8(D1[0], D1[1], D1[2], D1[3], a0, a1, a2, a3, vb0[8 + g], vb1[8 + g]);
    }

    sum0 += __shfl_xor_sync(0xffffffffu, sum0, 1);
    sum0 += __shfl_xor_sync(0xffffffffu, sum0, 2);
    sum1 += __shfl_xor_sync(0xffffffffu, sum1, 1);
    sum1 += __shfl_xor_sync(0xffffffffu, sum1, 2);

    int p0 = lineBase + r0, p1 = lineBase + r1;
    float gamma = gammap[0];
    float inv0 = __fdividef(gamma, sum0 + g_sH[p0]);
    float inv1 = __fdividef(gamma, sum1 + g_sH[p1]);

    // nt = 0: channels 2tig, 2tig+1 ; nt = 1: +8
    {
        float2 oh0 = unpack2(g_oH[(size_t)p0 * 8 + tig]);
        float2 oh1 = unpack2(g_oH[(size_t)p1 * 8 + tig]);
        int c = 2 * tig;
        y[c * Pn + p0]       = x[c * Pn + p0]       + (D0[0] + oh0.x) * inv0;
        y[(c + 1) * Pn + p0] = x[(c + 1) * Pn + p0] + (D0[1] + oh0.y) * inv0;
        y[c * Pn + p1]       = x[c * Pn + p1]       + (D0[2] + oh1.x) * inv1;
        y[(c + 1) * Pn + p1] = x[(c + 1) * Pn + p1] + (D0[3] + oh1.y) * inv1;
    }
    {
        float2 oh0 = unpack2(g_oH[(size_t)p0 * 8 + 4 + tig]);
        float2 oh1 = unpack2(g_oH[(size_t)p1 * 8 + 4 + tig]);
        int c = 8 + 2 * tig;
        y[c * Pn + p0]       = x[c * Pn + p0]       + (D1[0] + oh0.x) * inv0;
        y[(c + 1) * Pn + p0] = x[(c + 1) * Pn + p0] + (D1[1] + oh0.y) * inv0;
        y[c * Pn + p1]       = x[c * Pn + p1]       + (D1[2] + oh1.x) * inv1;
        y[(c + 1) * Pn + p1] = x[(c + 1) * Pn + p1] + (D1[3] + oh1.y) * inv1;
    }
}

// ---------------------------------------------------------------------------
extern "C" void kernel_launch(void* const* d_in, const int* in_sizes, int n_in,
                              void* d_out, int out_size)
{
    const float* x     = (const float*)d_in[0];
    const float* qw    = (const float*)d_in[1];
    const float* qb    = (const float*)d_in[2];
    const float* kw    = (const float*)d_in[3];
    const float* kb    = (const float*)d_in[4];
    const float* vw    = (const float*)d_in[5];
    const float* vb    = (const float*)d_in[6];
    const float* gamma = (const float*)d_in[7];
    float* out = (float*)d_out;

    dim3 gA(Wn, Dn);   // 192 x 24 blocks, 192 threads (1 column line each)
    dim3 gB(Hn, Dn);   // 96 x 24 blocks,  384 threads (1 row line each)
    int qkvBlocks = Pn / 256;

    qkv_kernel<<<qkvBlocks, 256>>>(x, qw, qb, kw, kb, vw, vb);
    passA_kernel<<<gA, 192>>>();
    passB_kernel<<<gB, 384>>>(x, nullptr, gamma);

    qkv_kernel<<<qkvBlocks, 256>>>(nullptr, qw, qb, kw, kb, vw, vb);
    passA_kernel<<<gA, 192>>>();
    passB_kernel<<<gB, 384>>>(nullptr, out, gamma);
}

// round 7
// speedup vs baseline: 2.5362x; 1.0352x over previous
#include <cuda_runtime.h>

#define Dn 24
#define Hn 96
#define Wn 192
#define HWn (Hn * Wn)          // 18432
#define Pn (Dn * HWn)          // 442368

typedef unsigned long long ull;
typedef unsigned int uint;

// Scratch (device globals — allocation forbidden)
__device__ float g_q[Pn * 2];      // [p][2], q pre-scaled by log2(e)
__device__ float g_k[Pn * 2];      // [p][2]
__device__ ull   g_v[Pn * 8];      // [p][8] channel pairs packed as 2xf32
__device__ float g_y[Pn * 16];     // intermediate image, [c][p]
__device__ float g_sH[Pn];
__device__ ull   g_oH[Pn * 8];     // unnormalized out_H, channel pairs

// ---- helpers ---------------------------------------------------------------
__device__ __forceinline__ void F2(ull& d, ull a, ull b, ull c) {
    asm("fma.rn.f32x2 %0,%1,%2,%3;" : "=l"(d) : "l"(a), "l"(b), "l"(c));
}
__device__ __forceinline__ ull pack2(float lo, float hi) {
    ull r; asm("mov.b64 %0,{%1,%2};" : "=l"(r) : "f"(lo), "f"(hi)); return r;
}
__device__ __forceinline__ ull dup2(float v) { return pack2(v, v); }
__device__ __forceinline__ float2 unpack2(ull v) {
    float2 r; asm("mov.b64 {%0,%1},%2;" : "=f"(r.x), "=f"(r.y) : "l"(v)); return r;
}
__device__ __forceinline__ float ex2f(float x) {
    float r; asm("ex2.approx.ftz.f32 %0,%1;" : "=f"(r) : "f"(x)); return r;
}
__device__ __forceinline__ uint tf32c(float f) {
    uint u; asm("cvt.rna.tf32.f32 %0,%1;" : "=r"(u) : "f"(f)); return u;
}
__device__ __forceinline__ void mma8(float& d0, float& d1, float& d2, float& d3,
                                     uint a0, uint a1, uint a2, uint a3,
                                     uint b0, uint b1) {
    asm("mma.sync.aligned.m16n8k8.row.col.f32.tf32.tf32.f32 "
        "{%0,%1,%2,%3},{%4,%5,%6,%7},{%8,%9},{%0,%1,%2,%3};"
        : "+f"(d0), "+f"(d1), "+f"(d2), "+f"(d3)
        : "r"(a0), "r"(a1), "r"(a2), "r"(a3), "r"(b0), "r"(b1));
}

#define L2E 1.44269504088896340736f

// ---------------------------------------------------------------------------
// QKV projection: 2 pixels/thread, float2 global loads (consecutive p).
// ---------------------------------------------------------------------------
__global__ __launch_bounds__(128) void qkv_kernel(const float* __restrict__ xin,
                           const float* __restrict__ qw, const float* __restrict__ qb,
                           const float* __restrict__ kw, const float* __restrict__ kb,
                           const float* __restrict__ vw, const float* __restrict__ vb)
{
    __shared__ float s_qw[32], s_kw[32], s_qb[2], s_kb[2];
    __shared__ ull s_vw[16][8];
    __shared__ ull s_vb[8];
    const float* x = xin ? xin : g_y;

    int t = threadIdx.x;
    {
        int c = t & 15, j = t >> 4;
        s_vw[c][j] = pack2(vw[(2 * j) * 16 + c], vw[(2 * j + 1) * 16 + c]);
    }
    if (t < 32)       s_qw[t]      = qw[t];
    else if (t < 64)  s_kw[t - 32] = kw[t - 32];
    else if (t < 66)  s_qb[t - 64] = qb[t - 64];
    else if (t < 68)  s_kb[t - 66] = kb[t - 66];
    else if (t < 76)  s_vb[t - 68] = pack2(vb[2 * (t - 68)], vb[2 * (t - 68) + 1]);
    __syncthreads();

    int p = blockIdx.x * 256 + 2 * t;   // 2 consecutive pixels

    float2 xv[16];
#pragma unroll
    for (int c = 0; c < 16; c++) xv[c] = *(const float2*)&x[c * Pn + p];

    float qa0 = s_qb[0], qa1 = s_qb[1], ka0 = s_kb[0], ka1 = s_kb[1];
    float qb0 = s_qb[0], qb1 = s_qb[1], kb0 = s_kb[0], kb1 = s_kb[1];
#pragma unroll
    for (int c = 0; c < 16; c++) {
        float wq0 = s_qw[c], wq1 = s_qw[16 + c], wk0 = s_kw[c], wk1 = s_kw[16 + c];
        qa0 = fmaf(wq0, xv[c].x, qa0);  qb0 = fmaf(wq0, xv[c].y, qb0);
        qa1 = fmaf(wq1, xv[c].x, qa1);  qb1 = fmaf(wq1, xv[c].y, qb1);
        ka0 = fmaf(wk0, xv[c].x, ka0);  kb0 = fmaf(wk0, xv[c].y, kb0);
        ka1 = fmaf(wk1, xv[c].x, ka1);  kb1 = fmaf(wk1, xv[c].y, kb1);
    }
    *(float4*)&g_q[p * 2] = make_float4(qa0 * L2E, qa1 * L2E, qb0 * L2E, qb1 * L2E);
    *(float4*)&g_k[p * 2] = make_float4(ka0, ka1, kb0, kb1);

    ull ava[8], avb[8];
#pragma unroll
    for (int j = 0; j < 8; j++) { ava[j] = s_vb[j]; avb[j] = s_vb[j]; }
#pragma unroll
    for (int c = 0; c < 16; c++) {
        ull xa = dup2(xv[c].x), xb = dup2(xv[c].y);
#pragma unroll
        for (int j = 0; j < 8; j++) {
            F2(ava[j], s_vw[c][j], xa, ava[j]);
            F2(avb[j], s_vw[c][j], xb, avb[j]);
        }
    }
    ulonglong2* vp = (ulonglong2*)&g_v[(size_t)p * 8];
    vp[0] = make_ulonglong2(ava[0], ava[1]);
    vp[1] = make_ulonglong2(ava[2], ava[3]);
    vp[2] = make_ulonglong2(ava[4], ava[5]);
    vp[3] = make_ulonglong2(ava[6], ava[7]);
    vp[4] = make_ulonglong2(avb[0], avb[1]);
    vp[5] = make_ulonglong2(avb[2], avb[3]);
    vp[6] = make_ulonglong2(avb[4], avb[5]);
    vp[7] = make_ulonglong2(avb[6], avb[7]);
}

// ---------------------------------------------------------------------------
// Pass A (MMA): 2 column lines per block. 12 warps; warps 0-5 -> col0, 6-11 -> col1.
// P computed scalar (raw fp32 bits as tf32); PV via mma; diag masked.
// ---------------------------------------------------------------------------
__global__ __launch_bounds__(384) void passA_kernel()
{
    __shared__ float2 s_q[2][96], s_k[2][96];
    __shared__ uint sV[2][96 * 24];    // tf32 V, row stride 24 (conflict-free)

    int d = blockIdx.y, t = threadIdx.x;
    int w2 = blockIdx.x * 2;

    if (t < 192) {
        int cc = t / 96, row = t % 96;
        int p = d * HWn + row * Wn + w2 + cc;
        s_q[cc][row] = ((const float2*)g_q)[p];
        s_k[cc][row] = ((const float2*)g_k)[p];
    }
    {
        int cc = t / 192, tt = t % 192;
        int row = tt >> 1, half = tt & 1;
        int p = d * HWn + row * Wn + w2 + cc;
        const ulonglong2* gv = (const ulonglong2*)&g_v[(size_t)p * 8 + half * 4];
        ulonglong2 u0 = gv[0], u1 = gv[1];
        uint* dst = &sV[cc][row * 24 + half * 8];
        float2 f;
        f = unpack2(u0.x); dst[0] = tf32c(f.x); dst[1] = tf32c(f.y);
        f = unpack2(u0.y); dst[2] = tf32c(f.x); dst[3] = tf32c(f.y);
        f = unpack2(u1.x); dst[4] = tf32c(f.x); dst[5] = tf32c(f.y);
        f = unpack2(u1.y); dst[6] = tf32c(f.x); dst[7] = tf32c(f.y);
    }
    __syncthreads();

    int warp = t >> 5, lane = t & 31, g = lane >> 2, tig = lane & 3;
    int col = warp / 6, warpIn = warp % 6;
    int lineBase = d * HWn + w2 + col;
    int r0 = warpIn * 16 + g, r1 = r0 + 8;
    float2 q0 = s_q[col][r0], q1 = s_q[col][r1];

    float D0[4] = {0, 0, 0, 0};
    float D1[4] = {0, 0, 0, 0};
    float sum0 = 0.f, sum1 = 0.f;

#pragma unroll 2
    for (int kt = 0; kt < 12; kt++) {
        int c0 = kt * 8 + tig, c1 = c0 + 4;
        float2 ka = s_k[col][c0], kb = s_k[col][c1];
        float e00 = fmaf(q0.y, ka.y, q0.x * ka.x);
        float e01 = fmaf(q0.y, kb.y, q0.x * kb.x);
        float e10 = fmaf(q1.y, ka.y, q1.x * ka.x);
        float e11 = fmaf(q1.y, kb.y, q1.x * kb.x);
        float p00 = (c0 == r0) ? 0.f : ex2f(e00);
        float p01 = (c1 == r0) ? 0.f : ex2f(e01);
        float p10 = (c0 == r1) ? 0.f : ex2f(e10);
        float p11 = (c1 == r1) ? 0.f : ex2f(e11);
        sum0 += p00 + p01;
        sum1 += p10 + p11;
        uint a0 = __float_as_uint(p00), a1 = __float_as_uint(p10);
        uint a2 = __float_as_uint(p01), a3 = __float_as_uint(p11);
        const uint* vb0 = &sV[col][c0 * 24];
        const uint* vb1 = &sV[col][c1 * 24];
        mma8(D0[0], D0[1], D0[2], D0[3], a0, a1, a2, a3, vb0[g],     vb1[g]);
        mma8(D1[0], D1[1], D1[2], D1[3], a0, a1, a2, a3, vb0[8 + g], vb1[8 + g]);
    }

    sum0 += __shfl_xor_sync(0xffffffffu, sum0, 1);
    sum0 += __shfl_xor_sync(0xffffffffu, sum0, 2);
    sum1 += __shfl_xor_sync(0xffffffffu, sum1, 1);
    sum1 += __shfl_xor_sync(0xffffffffu, sum1, 2);

    int p0 = lineBase + r0 * Wn, p1 = lineBase + r1 * Wn;
    if (tig == 0) { g_sH[p0] = sum0; g_sH[p1] = sum1; }
    g_oH[(size_t)p0 * 8 + tig]     = pack2(D0[0], D0[1]);
    g_oH[(size_t)p1 * 8 + tig]     = pack2(D0[2], D0[3]);
    g_oH[(size_t)p0 * 8 + 4 + tig] = pack2(D1[0], D1[1]);
    g_oH[(size_t)p1 * 8 + 4 + tig] = pack2(D1[2], D1[3]);
}

// ---------------------------------------------------------------------------
// Pass B (MMA): one row line per block. 12 warps x 16 queries = 192.
// Combine with H partials + residual in the epilogue.
// ---------------------------------------------------------------------------
__global__ __launch_bounds__(384) void passB_kernel(const float* __restrict__ xin,
                                                    float* __restrict__ dst,
                                                    const float* __restrict__ gammap)
{
    __shared__ float2 s_q[192], s_k[192];
    __shared__ uint sV[192 * 24];

    int d = blockIdx.y, h = blockIdx.x, t = threadIdx.x;
    int lineBase = d * HWn + h * Wn;          // p = lineBase + w
    const float* x = xin ? xin : g_y;
    float*       y = dst ? dst : g_y;

    if (t < 192) {
        int p = lineBase + t;
        s_q[t] = ((const float2*)g_q)[p];
        s_k[t] = ((const float2*)g_k)[p];
    }
#pragma unroll
    for (int kk = 0; kk < 4; kk++) {
        int f = t + kk * 384;                  // 0..1535
        int row = f >> 3, pair = f & 7;
        float2 fv = unpack2(g_v[(size_t)(lineBase + row) * 8 + pair]);
        sV[row * 24 + pair * 2]     = tf32c(fv.x);
        sV[row * 24 + pair * 2 + 1] = tf32c(fv.y);
    }
    __syncthreads();

    int warp = t >> 5, lane = t & 31, g = lane >> 2, tig = lane & 3;
    int r0 = warp * 16 + g, r1 = r0 + 8;
    float2 q0 = s_q[r0], q1 = s_q[r1];

    float D0[4] = {0, 0, 0, 0};
    float D1[4] = {0, 0, 0, 0};
    float sum0 = 0.f, sum1 = 0.f;

#pragma unroll 2
    for (int kt = 0; kt < 24; kt++) {
        int c0 = kt * 8 + tig, c1 = c0 + 4;
        float2 ka = s_k[c0], kb = s_k[c1];
        float e00 = fmaf(q0.y, ka.y, q0.x * ka.x);
        float e01 = fmaf(q0.y, kb.y, q0.x * kb.x);
        float e10 = fmaf(q1.y, ka.y, q1.x * ka.x);
        float e11 = fmaf(q1.y, kb.y, q1.x * kb.x);
        float p00 = ex2f(e00);
        float p01 = ex2f(e01);
        float p10 = ex2f(e10);
        float p11 = ex2f(e11);
        sum0 += p00 + p01;
        sum1 += p10 + p11;
        uint a0 = __float_as_uint(p00), a1 = __float_as_uint(p10);
        uint a2 = __float_as_uint(p01), a3 = __float_as_uint(p11);
        const uint* vb0 = &sV[c0 * 24];
        const uint* vb1 = &sV[c1 * 24];
        mma8(D0[0], D0[1], D0[2], D0[3], a0, a1, a2, a3, vb0[g],     vb1[g]);
        mma8(D1[0], D1[1], D1[2], D1[3], a0, a1, a2, a3, vb0[8 + g], vb1[8 + g]);
    }

    sum0 += __shfl_xor_sync(0xffffffffu, sum0, 1);
    sum0 += __shfl_xor_sync(0xffffffffu, sum0, 2);
    sum1 += __shfl_xor_sync(0xffffffffu, sum1, 1);
    sum1 += __shfl_xor_sync(0xffffffffu, sum1, 2);

    int p0 = lineBase + r0, p1 = lineBase + r1;
    float gamma = gammap[0];
    float inv0 = __fdividef(gamma, sum0 + g_sH[p0]);
    float inv1 = __fdividef(gamma, sum1 + g_sH[p1]);

    {
        float2 oh0 = unpack2(g_oH[(size_t)p0 * 8 + tig]);
        float2 oh1 = unpack2(g_oH[(size_t)p1 * 8 + tig]);
        int c = 2 * tig;
        y[c * Pn + p0]       = x[c * Pn + p0]       + (D0[0] + oh0.x) * inv0;
        y[(c + 1) * Pn + p0] = x[(c + 1) * Pn + p0] + (D0[1] + oh0.y) * inv0;
        y[c * Pn + p1]       = x[c * Pn + p1]       + (D0[2] + oh1.x) * inv1;
        y[(c + 1) * Pn + p1] = x[(c + 1) * Pn + p1] + (D0[3] + oh1.y) * inv1;
    }
    {
        float2 oh0 = unpack2(g_oH[(size_t)p0 * 8 + 4 + tig]);
        float2 oh1 = unpack2(g_oH[(size_t)p1 * 8 + 4 + tig]);
        int c = 8 + 2 * tig;
        y[c * Pn + p0]       = x[c * Pn + p0]       + (D1[0] + oh0.x) * inv0;
        y[(c + 1) * Pn + p0] = x[(c + 1) * Pn + p0] + (D1[1] + oh0.y) * inv0;
        y[c * Pn + p1]       = x[c * Pn + p1]       + (D1[2] + oh1.x) * inv1;
        y[(c + 1) * Pn + p1] = x[(c + 1) * Pn + p1] + (D1[3] + oh1.y) * inv1;
    }
}

// ---------------------------------------------------------------------------
extern "C" void kernel_launch(void* const* d_in, const int* in_sizes, int n_in,
                              void* d_out, int out_size)
{
    const float* x     = (const float*)d_in[0];
    const float* qw    = (const float*)d_in[1];
    const float* qb    = (const float*)d_in[2];
    const float* kw    = (const float*)d_in[3];
    const float* kb    = (const float*)d_in[4];
    const float* vw    = (const float*)d_in[5];
    const float* vb    = (const float*)d_in[6];
    const float* gamma = (const float*)d_in[7];
    float* out = (float*)d_out;

    dim3 gA(Wn / 2, Dn);   // 96 x 24 blocks, 384 threads (2 column lines each)
    dim3 gB(Hn, Dn);       // 96 x 24 blocks, 384 threads (1 row line each)
    int qkvBlocks = Pn / 256;   // 1728 blocks x 128 threads x 2 px

    qkv_kernel<<<qkvBlocks, 128>>>(x, qw, qb, kw, kb, vw, vb);
    passA_kernel<<<gA, 384>>>();
    passB_kernel<<<gB, 384>>>(x, nullptr, gamma);

    qkv_kernel<<<qkvBlocks, 128>>>(nullptr, qw, qb, kw, kb, vw, vb);
    passA_kernel<<<gA, 384>>>();
    passB_kernel<<<gB, 384>>>(nullptr, out, gamma);
}

// round 8
// speedup vs baseline: 3.0592x; 1.2062x over previous
#include <cuda_runtime.h>
#include <cuda_fp16.h>

#define Dn 24
#define Hn 96
#define Wn 192
#define HWn (Hn * Wn)          // 18432
#define Pn (Dn * HWn)          // 442368

typedef unsigned long long ull;
typedef unsigned int uint;

// Scratch (device globals — allocation forbidden)
__device__ float g_q[Pn * 2];      // [p][2], q pre-scaled by log2(e)
__device__ float g_k[Pn * 2];      // [p][2]
__device__ uint  g_vh[Pn * 8];     // [p][8] half2: channels (2j, 2j+1)
__device__ float g_y[Pn * 16];     // intermediate image, [c][p]
__device__ float g_sH[Pn];
__device__ uint  g_oh[Pn * 8];     // unnormalized out_H, half2 channel pairs

// ---- helpers ---------------------------------------------------------------
__device__ __forceinline__ void F2(ull& d, ull a, ull b, ull c) {
    asm("fma.rn.f32x2 %0,%1,%2,%3;" : "=l"(d) : "l"(a), "l"(b), "l"(c));
}
__device__ __forceinline__ ull pack2(float lo, float hi) {
    ull r; asm("mov.b64 %0,{%1,%2};" : "=l"(r) : "f"(lo), "f"(hi)); return r;
}
__device__ __forceinline__ ull dup2(float v) { return pack2(v, v); }
__device__ __forceinline__ float2 unpack2(ull v) {
    float2 r; asm("mov.b64 {%0,%1},%2;" : "=f"(r.x), "=f"(r.y) : "l"(v)); return r;
}
__device__ __forceinline__ float ex2f(float x) {
    float r; asm("ex2.approx.ftz.f32 %0,%1;" : "=f"(r) : "f"(x)); return r;
}
__device__ __forceinline__ uint h2pack(float lo, float hi) {   // {lo, hi}
    uint u; asm("cvt.rn.f16x2.f32 %0,%1,%2;" : "=r"(u) : "f"(hi), "f"(lo)); return u;
}
__device__ __forceinline__ float2 h2unpack(uint u) {
    __half2 h = *reinterpret_cast<__half2*>(&u);
    return __half22float2(h);
}
__device__ __forceinline__ void mmah(float& d0, float& d1, float& d2, float& d3,
                                     uint a0, uint a1, uint b0) {
    asm("mma.sync.aligned.m16n8k8.row.col.f32.f16.f16.f32 "
        "{%0,%1,%2,%3},{%4,%5},{%6},{%0,%1,%2,%3};"
        : "+f"(d0), "+f"(d1), "+f"(d2), "+f"(d3)
        : "r"(a0), "r"(a1), "r"(b0));
}

#define L2E 1.44269504088896340736f

// ---------------------------------------------------------------------------
// QKV projection: 2 pixels/thread; v stored fp16 (half2 channel pairs).
// ---------------------------------------------------------------------------
__global__ __launch_bounds__(128) void qkv_kernel(const float* __restrict__ xin,
                           const float* __restrict__ qw, const float* __restrict__ qb,
                           const float* __restrict__ kw, const float* __restrict__ kb,
                           const float* __restrict__ vw, const float* __restrict__ vb)
{
    __shared__ float s_qw[32], s_kw[32], s_qb[2], s_kb[2];
    __shared__ ull s_vw[16][8];
    __shared__ ull s_vb[8];
    const float* x = xin ? xin : g_y;

    int t = threadIdx.x;
    {
        int c = t & 15, j = t >> 4;
        s_vw[c][j] = pack2(vw[(2 * j) * 16 + c], vw[(2 * j + 1) * 16 + c]);
    }
    if (t < 32)       s_qw[t]      = qw[t];
    else if (t < 64)  s_kw[t - 32] = kw[t - 32];
    else if (t < 66)  s_qb[t - 64] = qb[t - 64];
    else if (t < 68)  s_kb[t - 66] = kb[t - 66];
    else if (t < 76)  s_vb[t - 68] = pack2(vb[2 * (t - 68)], vb[2 * (t - 68) + 1]);
    __syncthreads();

    int p = blockIdx.x * 256 + 2 * t;   // 2 consecutive pixels

    float2 xv[16];
#pragma unroll
    for (int c = 0; c < 16; c++) xv[c] = *(const float2*)&x[c * Pn + p];

    float qa0 = s_qb[0], qa1 = s_qb[1], ka0 = s_kb[0], ka1 = s_kb[1];
    float qb0 = s_qb[0], qb1 = s_qb[1], kb0 = s_kb[0], kb1 = s_kb[1];
#pragma unroll
    for (int c = 0; c < 16; c++) {
        float wq0 = s_qw[c], wq1 = s_qw[16 + c], wk0 = s_kw[c], wk1 = s_kw[16 + c];
        qa0 = fmaf(wq0, xv[c].x, qa0);  qb0 = fmaf(wq0, xv[c].y, qb0);
        qa1 = fmaf(wq1, xv[c].x, qa1);  qb1 = fmaf(wq1, xv[c].y, qb1);
        ka0 = fmaf(wk0, xv[c].x, ka0);  kb0 = fmaf(wk0, xv[c].y, kb0);
        ka1 = fmaf(wk1, xv[c].x, ka1);  kb1 = fmaf(wk1, xv[c].y, kb1);
    }
    *(float4*)&g_q[p * 2] = make_float4(qa0 * L2E, qa1 * L2E, qb0 * L2E, qb1 * L2E);
    *(float4*)&g_k[p * 2] = make_float4(ka0, ka1, kb0, kb1);

    ull ava[8], avb[8];
#pragma unroll
    for (int j = 0; j < 8; j++) { ava[j] = s_vb[j]; avb[j] = s_vb[j]; }
#pragma unroll
    for (int c = 0; c < 16; c++) {
        ull xa = dup2(xv[c].x), xb = dup2(xv[c].y);
#pragma unroll
        for (int j = 0; j < 8; j++) {
            F2(ava[j], s_vw[c][j], xa, ava[j]);
            F2(avb[j], s_vw[c][j], xb, avb[j]);
        }
    }
    uint ha[8], hb[8];
#pragma unroll
    for (int j = 0; j < 8; j++) {
        float2 fa = unpack2(ava[j]), fb = unpack2(avb[j]);
        ha[j] = h2pack(fa.x, fa.y);
        hb[j] = h2pack(fb.x, fb.y);
    }
    uint4* vp = (uint4*)&g_vh[(size_t)p * 8];
    vp[0] = make_uint4(ha[0], ha[1], ha[2], ha[3]);
    vp[1] = make_uint4(ha[4], ha[5], ha[6], ha[7]);
    vp[2] = make_uint4(hb[0], hb[1], hb[2], hb[3]);
    vp[3] = make_uint4(hb[4], hb[5], hb[6], hb[7]);
}

// ---------------------------------------------------------------------------
// Pass A (fp16 MMA): 2 column lines per block, 12 warps (6 per column).
// P scalar fp32 -> half2 A-fragments; V half2 B-fragments; diag masked.
// sVh rowpair stride 24 uints: B loads conflict-free.
// ---------------------------------------------------------------------------
__global__ __launch_bounds__(384) void passA_kernel()
{
    __shared__ __align__(16) float2 s_q[2][96], s_k[2][96];
    __shared__ uint sVh[2][48 * 24];   // [col][rowpair*24 + ch], half2 {v[2rp][ch], v[2rp+1][ch]}

    int d = blockIdx.y, t = threadIdx.x;
    int w2 = blockIdx.x * 2;

    if (t < 192) {
        int cc = t / 96, row = t % 96;
        int p = d * HWn + row * Wn + w2 + cc;
        s_q[cc][row] = ((const float2*)g_q)[p];
        s_k[cc][row] = ((const float2*)g_k)[p];
    } else {
        int t2 = t - 192;                 // 0..191
        int cc = t2 / 96, rem = t2 % 96;
        int rp = rem >> 1, hs = rem & 1;  // rowpair, half-select (ch 0-7 / 8-15)
        int pe = d * HWn + (2 * rp) * Wn + w2 + cc;
        int po = pe + Wn;
        uint4 e = *(const uint4*)&g_vh[(size_t)pe * 8 + hs * 4];
        uint4 o = *(const uint4*)&g_vh[(size_t)po * 8 + hs * 4];
        uint* dst = &sVh[cc][rp * 24 + hs * 8];
        dst[0] = __byte_perm(e.x, o.x, 0x5410); dst[1] = __byte_perm(e.x, o.x, 0x7632);
        dst[2] = __byte_perm(e.y, o.y, 0x5410); dst[3] = __byte_perm(e.y, o.y, 0x7632);
        dst[4] = __byte_perm(e.z, o.z, 0x5410); dst[5] = __byte_perm(e.z, o.z, 0x7632);
        dst[6] = __byte_perm(e.w, o.w, 0x5410); dst[7] = __byte_perm(e.w, o.w, 0x7632);
    }
    __syncthreads();

    int warp = t >> 5, lane = t & 31, g = lane >> 2, tig = lane & 3;
    int col = warp / 6, warpIn = warp % 6;
    int lineBase = d * HWn + w2 + col;
    int r0 = warpIn * 16 + g, r1 = r0 + 8;
    float2 q0 = s_q[col][r0], q1 = s_q[col][r1];

    float D0[4] = {0, 0, 0, 0};
    float D1[4] = {0, 0, 0, 0};
    float sum0 = 0.f, sum1 = 0.f;

#pragma unroll 2
    for (int kt = 0; kt < 12; kt++) {
        int c0 = kt * 8 + 2 * tig;
        float4 kk = *(const float4*)&s_k[col][c0];   // k[c0], k[c0+1]
        float e00 = fmaf(q0.y, kk.y, q0.x * kk.x);
        float e01 = fmaf(q0.y, kk.w, q0.x * kk.z);
        float e10 = fmaf(q1.y, kk.y, q1.x * kk.x);
        float e11 = fmaf(q1.y, kk.w, q1.x * kk.z);
        float p00 = (c0 == r0)     ? 0.f : ex2f(e00);
        float p01 = (c0 + 1 == r0) ? 0.f : ex2f(e01);
        float p10 = (c0 == r1)     ? 0.f : ex2f(e10);
        float p11 = (c0 + 1 == r1) ? 0.f : ex2f(e11);
        sum0 += p00 + p01;
        sum1 += p10 + p11;
        uint a0 = h2pack(p00, p01);
        uint a1 = h2pack(p10, p11);
        int rp = kt * 4 + tig;
        uint b0 = sVh[col][rp * 24 + g];
        uint b1 = sVh[col][rp * 24 + 8 + g];
        mmah(D0[0], D0[1], D0[2], D0[3], a0, a1, b0);
        mmah(D1[0], D1[1], D1[2], D1[3], a0, a1, b1);
    }

    sum0 += __shfl_xor_sync(0xffffffffu, sum0, 1);
    sum0 += __shfl_xor_sync(0xffffffffu, sum0, 2);
    sum1 += __shfl_xor_sync(0xffffffffu, sum1, 1);
    sum1 += __shfl_xor_sync(0xffffffffu, sum1, 2);

    int p0 = lineBase + r0 * Wn, p1 = lineBase + r1 * Wn;
    if (tig == 0) { g_sH[p0] = sum0; g_sH[p1] = sum1; }
    g_oh[(size_t)p0 * 8 + tig]     = h2pack(D0[0], D0[1]);
    g_oh[(size_t)p1 * 8 + tig]     = h2pack(D0[2], D0[3]);
    g_oh[(size_t)p0 * 8 + 4 + tig] = h2pack(D1[0], D1[1]);
    g_oh[(size_t)p1 * 8 + 4 + tig] = h2pack(D1[2], D1[3]);
}

// ---------------------------------------------------------------------------
// Pass B (fp16 MMA): one row line per block, 12 warps. Combine + residual.
// ---------------------------------------------------------------------------
__global__ __launch_bounds__(384) void passB_kernel(const float* __restrict__ xin,
                                                    float* __restrict__ dst,
                                                    const float* __restrict__ gammap)
{
    __shared__ __align__(16) float2 s_q[192], s_k[192];
    __shared__ uint sVh[96 * 24];

    int d = blockIdx.y, h = blockIdx.x, t = threadIdx.x;
    int lineBase = d * HWn + h * Wn;
    const float* x = xin ? xin : g_y;
    float*       y = dst ? dst : g_y;

    if (t < 192) {
        int p = lineBase + t;
        s_q[t] = ((const float2*)g_q)[p];
        s_k[t] = ((const float2*)g_k)[p];
    } else {
        int t2 = t - 192;                 // 0..191
        int rp = t2 >> 1, hs = t2 & 1;
        int pe = lineBase + 2 * rp;
        uint4 e = *(const uint4*)&g_vh[(size_t)pe * 8 + hs * 4];
        uint4 o = *(const uint4*)&g_vh[(size_t)(pe + 1) * 8 + hs * 4];
        uint* dstp = &sVh[rp * 24 + hs * 8];
        dstp[0] = __byte_perm(e.x, o.x, 0x5410); dstp[1] = __byte_perm(e.x, o.x, 0x7632);
        dstp[2] = __byte_perm(e.y, o.y, 0x5410); dstp[3] = __byte_perm(e.y, o.y, 0x7632);
        dstp[4] = __byte_perm(e.z, o.z, 0x5410); dstp[5] = __byte_perm(e.z, o.z, 0x7632);
        dstp[6] = __byte_perm(e.w, o.w, 0x5410); dstp[7] = __byte_perm(e.w, o.w, 0x7632);
    }
    __syncthreads();

    int warp = t >> 5, lane = t & 31, g = lane >> 2, tig = lane & 3;
    int r0 = warp * 16 + g, r1 = r0 + 8;
    float2 q0 = s_q[r0], q1 = s_q[r1];

    float D0[4] = {0, 0, 0, 0};
    float D1[4] = {0, 0, 0, 0};
    float sum0 = 0.f, sum1 = 0.f;

#pragma unroll 2
    for (int kt = 0; kt < 24; kt++) {
        int c0 = kt * 8 + 2 * tig;
        float4 kk = *(const float4*)&s_k[c0];
        float e00 = fmaf(q0.y, kk.y, q0.x * kk.x);
        float e01 = fmaf(q0.y, kk.w, q0.x * kk.z);
        float e10 = fmaf(q1.y, kk.y, q1.x * kk.x);
        float e11 = fmaf(q1.y, kk.w, q1.x * kk.z);
        float p00 = ex2f(e00);
        float p01 = ex2f(e01);
        float p10 = ex2f(e10);
        float p11 = ex2f(e11);
        sum0 += p00 + p01;
        sum1 += p10 + p11;
        uint a0 = h2pack(p00, p01);
        uint a1 = h2pack(p10, p11);
        int rp = kt * 4 + tig;
        uint b0 = sVh[rp * 24 + g];
        uint b1 = sVh[rp * 24 + 8 + g];
        mmah(D0[0], D0[1], D0[2], D0[3], a0, a1, b0);
        mmah(D1[0], D1[1], D1[2], D1[3], a0, a1, b1);
    }

    sum0 += __shfl_xor_sync(0xffffffffu, sum0, 1);
    sum0 += __shfl_xor_sync(0xffffffffu, sum0, 2);
    sum1 += __shfl_xor_sync(0xffffffffu, sum1, 1);
    sum1 += __shfl_xor_sync(0xffffffffu, sum1, 2);

    int p0 = lineBase + r0, p1 = lineBase + r1;
    float gamma = gammap[0];
    float inv0 = __fdividef(gamma, sum0 + g_sH[p0]);
    float inv1 = __fdividef(gamma, sum1 + g_sH[p1]);

    {
        float2 oh0 = h2unpack(g_oh[(size_t)p0 * 8 + tig]);
        float2 oh1 = h2unpack(g_oh[(size_t)p1 * 8 + tig]);
        int c = 2 * tig;
        y[c * Pn + p0]       = x[c * Pn + p0]       + (D0[0] + oh0.x) * inv0;
        y[(c + 1) * Pn + p0] = x[(c + 1) * Pn + p0] + (D0[1] + oh0.y) * inv0;
        y[c * Pn + p1]       = x[c * Pn + p1]       + (D0[2] + oh1.x) * inv1;
        y[(c + 1) * Pn + p1] = x[(c + 1) * Pn + p1] + (D0[3] + oh1.y) * inv1;
    }
    {
        float2 oh0 = h2unpack(g_oh[(size_t)p0 * 8 + 4 + tig]);
        float2 oh1 = h2unpack(g_oh[(size_t)p1 * 8 + 4 + tig]);
        int c = 8 + 2 * tig;
        y[c * Pn + p0]       = x[c * Pn + p0]       + (D1[0] + oh0.x) * inv0;
        y[(c + 1) * Pn + p0] = x[(c + 1) * Pn + p0] + (D1[1] + oh0.y) * inv0;
        y[c * Pn + p1]       = x[c * Pn + p1]       + (D1[2] + oh1.x) * inv1;
        y[(c + 1) * Pn + p1] = x[(c + 1) * Pn + p1] + (D1[3] + oh1.y) * inv1;
    }
}

// ---------------------------------------------------------------------------
extern "C" void kernel_launch(void* const* d_in, const int* in_sizes, int n_in,
                              void* d_out, int out_size)
{
    const float* x     = (const float*)d_in[0];
    const float* qw    = (const float*)d_in[1];
    const float* qb    = (const float*)d_in[2];
    const float* kw    = (const float*)d_in[3];
    const float* kb    = (const float*)d_in[4];
    const float* vw    = (const float*)d_in[5];
    const float* vb    = (const float*)d_in[6];
    const float* gamma = (const float*)d_in[7];
    float* out = (float*)d_out;

    dim3 gA(Wn / 2, Dn);   // 96 x 24 blocks, 384 threads
    dim3 gB(Hn, Dn);       // 96 x 24 blocks, 384 threads
    int qkvBlocks = Pn / 256;

    qkv_kernel<<<qkvBlocks, 128>>>(x, qw, qb, kw, kb, vw, vb);
    passA_kernel<<<gA, 384>>>();
    passB_kernel<<<gB, 384>>>(x, nullptr, gamma);

    qkv_kernel<<<qkvBlocks, 128>>>(nullptr, qw, qb, kw, kb, vw, vb);
    passA_kernel<<<gA, 384>>>();
    passB_kernel<<<gB, 384>>>(nullptr, out, gamma);
}